// round 11
// baseline (speedup 1.0000x reference)
#include <cuda_runtime.h>
#include <cuda_fp16.h>
#include <stdint.h>

typedef __half f16;

#define BATCH 4
#define SEQ   2048
#define DMOD  1024

#define NQ ((long)BATCH*SEQ*DMOD)   // 8,388,608
#define NW ((long)DMOD*DMOD)        // 1,048,576
#define NS ((long)BATCH*SEQ*SEQ)    // 16,777,216

// ----------------------------------------------------------------------------
// Scratch (device globals; allocation is forbidden)
// ----------------------------------------------------------------------------
__device__ __align__(256) f16 g_xq[NQ], g_xk[NQ], g_xv[NQ];        // inputs, single fp16
__device__ __align__(256) f16 g_wq_hi[NW], g_wq_lo[NW];
__device__ __align__(256) f16 g_wk_hi[NW], g_wk_lo[NW];
__device__ __align__(256) f16 g_wv_hi[NW], g_wv_lo[NW];
__device__ __align__(256) f16 g_wo_hi[NW], g_wo_lo[NW];
__device__ __align__(256) f16 g_qp[NQ];                            // q-proj, single
__device__ __align__(256) f16 g_kp_hi[NQ], g_kp_lo[NQ];            // k-proj, pair
__device__ __align__(256) f16 g_vT_hi[NQ], g_vT_lo[NQ];            // v-proj transposed [B][D][S], pair
__device__ __align__(256) float g_sc[NS];                          // scores fp32
__device__ __align__(256) f16 g_at[NS];                            // probs, single
__device__ __align__(256) f16 g_av[NQ];                            // attn@V, single

// ----------------------------------------------------------------------------
// helpers
// ----------------------------------------------------------------------------
__device__ __forceinline__ uint32_t smem_u32(const void* p) {
    uint32_t a;
    asm("{ .reg .u64 t; cvta.to.shared.u64 t, %1; cvt.u32.u64 %0, t; }" : "=r"(a) : "l"(p));
    return a;
}
__device__ __forceinline__ void cp16(uint32_t s, const void* g) {
    asm volatile("cp.async.cg.shared.global [%0], [%1], 16;" :: "r"(s), "l"(g));
}
#define CP_COMMIT() asm volatile("cp.async.commit_group;" ::: "memory")
#define CP_WAIT(n)  asm volatile("cp.async.wait_group %0;" :: "n"(n) : "memory")

__device__ __forceinline__ void ldsm4(uint32_t& r0, uint32_t& r1, uint32_t& r2,
                                      uint32_t& r3, uint32_t addr) {
    asm volatile("ldmatrix.sync.aligned.m8n8.x4.shared.b16 {%0,%1,%2,%3}, [%4];"
                 : "=r"(r0), "=r"(r1), "=r"(r2), "=r"(r3) : "r"(addr));
}
__device__ __forceinline__ void mma16816(float* d, const uint32_t* a, const uint32_t* b) {
    asm volatile(
        "mma.sync.aligned.m16n8k16.row.col.f32.f16.f16.f32 "
        "{%0,%1,%2,%3}, {%4,%5,%6,%7}, {%8,%9}, {%0,%1,%2,%3};"
        : "+f"(d[0]), "+f"(d[1]), "+f"(d[2]), "+f"(d[3])
        : "r"(a[0]), "r"(a[1]), "r"(a[2]), "r"(a[3]), "r"(b[0]), "r"(b[1]));
}

// ----------------------------------------------------------------------------
// fused conversions
// ----------------------------------------------------------------------------
__global__ void conv_x3(const float* __restrict__ q, const float* __restrict__ k,
                        const float* __restrict__ v) {
    long i = (long)blockIdx.x * blockDim.x + threadIdx.x;
    if (i >= 3 * NQ) return;
    const float* src; f16* dst; long j;
    if (i < NQ)          { src = q; dst = g_xq; j = i; }
    else if (i < 2 * NQ) { src = k; dst = g_xk; j = i - NQ; }
    else                 { src = v; dst = g_xv; j = i - 2 * NQ; }
    dst[j] = __float2half_rn(src[j]);
}

__global__ void split_w4(const float* __restrict__ wq, const float* __restrict__ wk,
                         const float* __restrict__ wv, const float* __restrict__ wo) {
    long i = (long)blockIdx.x * blockDim.x + threadIdx.x;
    if (i >= 4 * NW) return;
    const float* src; f16 *hi, *lo; long j;
    if (i < NW)          { src = wq; hi = g_wq_hi; lo = g_wq_lo; j = i; }
    else if (i < 2 * NW) { src = wk; hi = g_wk_hi; lo = g_wk_lo; j = i - NW; }
    else if (i < 3 * NW) { src = wv; hi = g_wv_hi; lo = g_wv_lo; j = i - 2 * NW; }
    else                 { src = wo; hi = g_wo_hi; lo = g_wo_lo; j = i - 3 * NW; }
    float val = src[j];
    f16 h = __float2half_rn(val);
    hi[j] = h;
    lo[j] = __float2half_rn(val - __half2float(h));
}

// ----------------------------------------------------------------------------
// Row softmax fp32 -> fp16   (n == 2048, 256 threads)
// ----------------------------------------------------------------------------
__global__ void softmax_f16(const float* __restrict__ S, f16* __restrict__ P, int n) {
    const float* row = S + (long)blockIdx.x * n;
    __shared__ float red[256];
    const int t = threadIdx.x;
    float e[8];
    float m = -1e30f;
#pragma unroll
    for (int i = 0; i < 8; i++) { e[i] = row[t + i * 256]; m = fmaxf(m, e[i]); }
    red[t] = m; __syncthreads();
    for (int s = 128; s > 0; s >>= 1) {
        if (t < s) red[t] = fmaxf(red[t], red[t + s]);
        __syncthreads();
    }
    m = red[0]; __syncthreads();
    float sum = 0.f;
#pragma unroll
    for (int i = 0; i < 8; i++) { e[i] = __expf(e[i] - m); sum += e[i]; }
    red[t] = sum; __syncthreads();
    for (int s = 128; s > 0; s >>= 1) {
        if (t < s) red[t] += red[t + s];
        __syncthreads();
    }
    float inv = 1.0f / red[0];
#pragma unroll
    for (int i = 0; i < 8; i++)
        P[(long)blockIdx.x * n + t + i * 256] = __float2half_rn(e[i] * inv);
}

// ----------------------------------------------------------------------------
// mma.sync fp16 2-product GEMM (NT):  C[m,n] = alpha * sum_k A[m,k]*B[n,k] (+bias)
//   A single fp16, B = Bh + Bl fp16 pair.
//   CTA tile 128x128, BK=32, 2-stage cp.async, 4 warps (64x64 each), 128 thr.
//   Fat warp tile: 16 LDSM feed 128 HMMA per chunk (8:1 ratio).
//   mode 0: fp32 out.  mode 1: fp16 single out.  mode 2: fp16 pair out.
// ----------------------------------------------------------------------------
#define BM 128
#define BN 128
#define BK 32
#define ROWB 80              // smem row stride bytes (32 fp16 = 64B data + 16B pad)
#define TILEB (128 * ROWB)   // 10240 B per matrix tile
#define SM_A  0
#define SM_BH TILEB
#define SM_BL (2 * TILEB)
#define STAGEB (3 * TILEB)   // 30720 B
#define SMEM_BYTES (2 * STAGEB)   // 61440 B

__global__ void __launch_bounds__(128, 2) gemm2(
    const f16* __restrict__ A,
    const f16* __restrict__ Bhi, const f16* __restrict__ Blo,
    const float* __restrict__ bias,
    float* __restrict__ Cf, f16* __restrict__ C1, f16* __restrict__ C2,
    int N, int K, int ldc, float alpha,
    long sA, long sB, long sC, int mode, int transC)
{
    extern __shared__ char smem[];
    const uint32_t sb = smem_u32(smem);
    const int tid = threadIdx.x;
    const int wid = tid >> 5;            // 0..3
    const int lid = tid & 31;
    const int wm = (wid & 1) * 64;       // warp M offset in CTA tile
    const int wn = (wid >> 1) * 64;      // warp N offset
    const long bz = blockIdx.z;
    const int m0 = blockIdx.y * BM;
    const int n0 = blockIdx.x * BN;

    const f16* pA  = A   + bz * sA;
    const f16* pBh = Bhi + bz * sB;
    const f16* pBl = Blo + bz * sB;

    float acc[4][8][4];                  // 64x64 warp tile: 128 fp32/thread
#pragma unroll
    for (int i = 0; i < 4; ++i)
#pragma unroll
        for (int j = 0; j < 8; ++j)
#pragma unroll
            for (int c = 0; c < 4; ++c) acc[i][j][c] = 0.f;

    const int nch = K / BK;

    // ---- stage loader: 12 x cp.async per thread (1 row x 3 tiles x 64B) ----
    auto issue = [&](int ch, int buf) {
        const int k0 = ch * BK;
        const uint32_t s0 = sb + buf * STAGEB;
        const uint32_t so = (uint32_t)(tid * ROWB);
        const long goA = (long)(m0 + tid) * K + k0;
        const long goB = (long)(n0 + tid) * K + k0;
#pragma unroll
        for (int j = 0; j < 4; ++j) {
            cp16(s0 + SM_A  + so + j * 16, pA  + goA + j * 8);
            cp16(s0 + SM_BH + so + j * 16, pBh + goB + j * 8);
            cp16(s0 + SM_BL + so + j * 16, pBl + goB + j * 8);
        }
    };

    issue(0, 0);
    CP_COMMIT();

    // ldmatrix lane addressing (within a stage buffer)
    const int a_row = lid & 15;                    // 0..15
    const int a_col = (lid >> 4) * 16;             // 0 or 16 bytes
    const int b_nin = ((lid >> 4) & 1) * 8 + (lid & 7);  // n within 16-block
    const int b_col = ((lid >> 3) & 1) * 16;       // k-half bytes

    for (int ch = 0; ch < nch; ++ch) {
        if (ch + 1 < nch) { issue(ch + 1, (ch + 1) & 1); CP_COMMIT(); CP_WAIT(1); }
        else              { CP_WAIT(0); }
        __syncthreads();

        const uint32_t s0 = sb + (ch & 1) * STAGEB;

#pragma unroll
        for (int ks = 0; ks < 2; ++ks) {
            const int kb = ks * 32 + a_col;        // A k-byte offset for this lane
            uint32_t af[4][4];
#pragma unroll
            for (int mt = 0; mt < 4; ++mt) {
                const uint32_t ro = (uint32_t)((wm + mt * 16 + a_row) * ROWB);
                ldsm4(af[mt][0], af[mt][1], af[mt][2], af[mt][3], s0 + SM_A + ro + kb);
            }
            // per-n-pair B loads, then dense 16-MMA burst
#pragma unroll
            for (int np = 0; np < 4; ++np) {
                uint32_t bh[4], bl[4];
                const uint32_t ro = (uint32_t)((wn + np * 16 + b_nin) * ROWB + ks * 32 + b_col);
                ldsm4(bh[0], bh[1], bh[2], bh[3], s0 + SM_BH + ro);
                ldsm4(bl[0], bl[1], bl[2], bl[3], s0 + SM_BL + ro);
#pragma unroll
                for (int mt = 0; mt < 4; ++mt) {
#pragma unroll
                    for (int t = 0; t < 2; ++t) {
                        const int nt = np * 2 + t;
                        mma16816(acc[mt][nt], af[mt], &bh[t * 2]);
                        mma16816(acc[mt][nt], af[mt], &bl[t * 2]);
                    }
                }
            }
        }
        __syncthreads();
    }

    // ---- epilogue ----
    const int gr = lid >> 2;             // group row 0..7
    const int tg = lid & 3;              // col pair 0..3
#pragma unroll
    for (int mt = 0; mt < 4; ++mt) {
#pragma unroll
        for (int nt = 0; nt < 8; ++nt) {
#pragma unroll
            for (int h = 0; h < 2; ++h) {        // c0c1 vs c2c3 (row +8)
                const int m = m0 + wm + mt * 16 + gr + h * 8;
#pragma unroll
                for (int c = 0; c < 2; ++c) {
                    const int n = n0 + wn + nt * 8 + tg * 2 + c;
                    float v = acc[mt][nt][h * 2 + c] * alpha;
                    if (bias) v += __ldg(bias + n);
                    if (mode == 0) {
                        Cf[bz * sC + (long)m * ldc + n] = v;
                    } else {
                        long o = transC ? (bz * sC + (long)n * ldc + m)
                                        : (bz * sC + (long)m * ldc + n);
                        f16 hh = __float2half_rn(v);
                        C1[o] = hh;
                        if (mode == 2)
                            C2[o] = __float2half_rn(v - __half2float(hh));
                    }
                }
            }
        }
    }
}

// ----------------------------------------------------------------------------
// launch
// ----------------------------------------------------------------------------
extern "C" void kernel_launch(void* const* d_in, const int* in_sizes, int n_in,
                              void* d_out, int out_size) {
    const float* q  = (const float*)d_in[0];
    const float* k  = (const float*)d_in[1];
    const float* v  = (const float*)d_in[2];
    const float* Wq = (const float*)d_in[3];
    const float* bq = (const float*)d_in[4];
    const float* Wk = (const float*)d_in[5];
    const float* bk = (const float*)d_in[6];
    const float* Wv = (const float*)d_in[7];
    const float* bv = (const float*)d_in[8];
    const float* Wo = (const float*)d_in[9];
    const float* bo = (const float*)d_in[10];
    float* out = (float*)d_out;

    f16 *xq, *xk, *xv, *qp, *at, *av;
    f16 *wqh, *wql, *wkh, *wkl, *wvh, *wvl, *woh, *wol;
    f16 *kph, *kpl, *vTh, *vTl;
    float* sc;
    cudaGetSymbolAddress((void**)&xq, g_xq);
    cudaGetSymbolAddress((void**)&xk, g_xk);
    cudaGetSymbolAddress((void**)&xv, g_xv);
    cudaGetSymbolAddress((void**)&wqh, g_wq_hi); cudaGetSymbolAddress((void**)&wql, g_wq_lo);
    cudaGetSymbolAddress((void**)&wkh, g_wk_hi); cudaGetSymbolAddress((void**)&wkl, g_wk_lo);
    cudaGetSymbolAddress((void**)&wvh, g_wv_hi); cudaGetSymbolAddress((void**)&wvl, g_wv_lo);
    cudaGetSymbolAddress((void**)&woh, g_wo_hi); cudaGetSymbolAddress((void**)&wol, g_wo_lo);
    cudaGetSymbolAddress((void**)&qp, g_qp);
    cudaGetSymbolAddress((void**)&kph, g_kp_hi); cudaGetSymbolAddress((void**)&kpl, g_kp_lo);
    cudaGetSymbolAddress((void**)&vTh, g_vT_hi); cudaGetSymbolAddress((void**)&vTl, g_vT_lo);
    cudaGetSymbolAddress((void**)&at, g_at);
    cudaGetSymbolAddress((void**)&av, g_av);
    cudaGetSymbolAddress((void**)&sc, g_sc);

    cudaFuncSetAttribute(gemm2, cudaFuncAttributeMaxDynamicSharedMemorySize, SMEM_BYTES);

    const int D = DMOD, S = SEQ, B = BATCH;
    dim3 blk(128);
    dim3 gp(D / BN, (B * S) / BM, 1);    // (8, 64)
    dim3 gv(D / BN, S / BM, B);          // (8, 16, 4)
    dim3 gs(S / BN, S / BM, B);          // (16, 16, 4)
    dim3 ga(D / BN, S / BM, B);          // (8, 16, 4)

    // 1-2: fused conversions
    conv_x3 <<<(unsigned)((3 * NQ + 511) / 512), 512>>>(q, k, v);
    split_w4<<<(unsigned)((4 * NW + 511) / 512), 512>>>(Wq, Wk, Wv, Wo);

    // 3: q projection -> qp (fp16 single)
    gemm2<<<gp, blk, SMEM_BYTES>>>(xq, wqh, wql, bq, nullptr, qp, nullptr,
                                   D, D, D, 1.0f, 0, 0, 0, 1, 0);
    // 4: k projection -> kp (fp16 pair)
    gemm2<<<gp, blk, SMEM_BYTES>>>(xk, wkh, wkl, bk, nullptr, kph, kpl,
                                   D, D, D, 1.0f, 0, 0, 0, 2, 0);
    // 5: v projection -> vT (fp16 pair, transposed [B][D][S])
    gemm2<<<gv, blk, SMEM_BYTES>>>(xv, wvh, wvl, bv, nullptr, vTh, vTl,
                                   D, D, /*ldc=*/S, 1.0f,
                                   (long)S * D, 0, (long)D * S, 2, 1);
    // 6: scores = qp @ kp^T * 0.125 -> fp32           <-- ncu -s 5 -c 1 capture
    gemm2<<<gs, blk, SMEM_BYTES>>>(qp, kph, kpl, nullptr, sc, nullptr, nullptr,
                                   S, D, S, 0.125f,
                                   (long)S * D, (long)S * D, (long)S * S, 0, 0);
    // 7: softmax -> fp16 probs
    softmax_f16<<<(unsigned)(B * S), 256>>>(sc, at, S);
    // 8: att = probs @ vT^T -> fp16 single
    gemm2<<<ga, blk, SMEM_BYTES>>>(at, vTh, vTl, nullptr, nullptr, av, nullptr,
                                   D, S, D, 1.0f,
                                   (long)S * S, (long)D * S, (long)S * D, 1, 0);
    // 9: out = att @ Wo^T + bo -> fp32
    gemm2<<<gp, blk, SMEM_BYTES>>>(av, woh, wol, bo, out, nullptr, nullptr,
                                   D, D, D, 1.0f, 0, 0, 0, 0, 0);
}

// round 12
// speedup vs baseline: 1.4607x; 1.4607x over previous
#include <cuda_runtime.h>
#include <cuda_fp16.h>
#include <stdint.h>

typedef __half f16;

#define BATCH 4
#define SEQ   2048
#define DMOD  1024

#define NQ ((long)BATCH*SEQ*DMOD)   // 8,388,608
#define NW ((long)DMOD*DMOD)        // 1,048,576
#define NS ((long)BATCH*SEQ*SEQ)    // 16,777,216

// ----------------------------------------------------------------------------
// Scratch (device globals; allocation is forbidden)
// ----------------------------------------------------------------------------
__device__ __align__(256) f16 g_xq_hi[NQ], g_xq_lo[NQ];            // q input, pair
__device__ __align__(256) f16 g_xk_hi[NQ], g_xk_lo[NQ];            // k input, pair
__device__ __align__(256) f16 g_xv[NQ];                            // v input, single
__device__ __align__(256) f16 g_wq_hi[NW], g_wq_lo[NW];
__device__ __align__(256) f16 g_wk_hi[NW], g_wk_lo[NW];
__device__ __align__(256) f16 g_wv_hi[NW], g_wv_lo[NW];
__device__ __align__(256) f16 g_wo[NW];                            // Wo, single
__device__ __align__(256) f16 g_qp[NQ];                            // q-proj, single
__device__ __align__(256) f16 g_kp_hi[NQ], g_kp_lo[NQ];            // k-proj, pair
__device__ __align__(256) f16 g_vT[NQ];                            // v-proj [B][D][S], single
__device__ __align__(256) float g_sc[NS];                          // scores fp32
__device__ __align__(256) f16 g_at[NS];                            // probs, single
__device__ __align__(256) f16 g_av[NQ];                            // attn@V, single

// ----------------------------------------------------------------------------
// helpers
// ----------------------------------------------------------------------------
__device__ __forceinline__ uint32_t smem_u32(const void* p) {
    uint32_t a;
    asm("{ .reg .u64 t; cvta.to.shared.u64 t, %1; cvt.u32.u64 %0, t; }" : "=r"(a) : "l"(p));
    return a;
}
__device__ __forceinline__ void cp16(uint32_t s, const void* g) {
    asm volatile("cp.async.cg.shared.global [%0], [%1], 16;" :: "r"(s), "l"(g));
}
#define CP_COMMIT() asm volatile("cp.async.commit_group;" ::: "memory")
#define CP_WAIT(n)  asm volatile("cp.async.wait_group %0;" :: "n"(n) : "memory")

__device__ __forceinline__ void ldsm4(uint32_t& r0, uint32_t& r1, uint32_t& r2,
                                      uint32_t& r3, uint32_t addr) {
    asm volatile("ldmatrix.sync.aligned.m8n8.x4.shared.b16 {%0,%1,%2,%3}, [%4];"
                 : "=r"(r0), "=r"(r1), "=r"(r2), "=r"(r3) : "r"(addr));
}
__device__ __forceinline__ void mma16816(float* d, const uint32_t* a, const uint32_t* b) {
    asm volatile(
        "mma.sync.aligned.m16n8k16.row.col.f32.f16.f16.f32 "
        "{%0,%1,%2,%3}, {%4,%5,%6,%7}, {%8,%9}, {%0,%1,%2,%3};"
        : "+f"(d[0]), "+f"(d[1]), "+f"(d[2]), "+f"(d[3])
        : "r"(a[0]), "r"(a[1]), "r"(a[2]), "r"(a[3]), "r"(b[0]), "r"(b[1]));
}

// ----------------------------------------------------------------------------
// fused conversions
// ----------------------------------------------------------------------------
// q,k -> fp16 pairs; v -> fp16 single
__global__ void conv_inputs(const float* __restrict__ q, const float* __restrict__ k,
                            const float* __restrict__ v) {
    long i = (long)blockIdx.x * blockDim.x + threadIdx.x;
    if (i >= 3 * NQ) return;
    if (i < NQ) {
        float val = q[i];
        f16 h = __float2half_rn(val);
        g_xq_hi[i] = h;
        g_xq_lo[i] = __float2half_rn(val - __half2float(h));
    } else if (i < 2 * NQ) {
        long j = i - NQ;
        float val = k[j];
        f16 h = __float2half_rn(val);
        g_xk_hi[j] = h;
        g_xk_lo[j] = __float2half_rn(val - __half2float(h));
    } else {
        long j = i - 2 * NQ;
        g_xv[j] = __float2half_rn(v[j]);
    }
}

// Wq,Wk,Wv -> fp16 pairs; Wo -> fp16 single
__global__ void conv_weights(const float* __restrict__ wq, const float* __restrict__ wk,
                             const float* __restrict__ wv, const float* __restrict__ wo) {
    long i = (long)blockIdx.x * blockDim.x + threadIdx.x;
    if (i >= 4 * NW) return;
    if (i < 3 * NW) {
        const float* src; f16 *hi, *lo; long j;
        if (i < NW)          { src = wq; hi = g_wq_hi; lo = g_wq_lo; j = i; }
        else if (i < 2 * NW) { src = wk; hi = g_wk_hi; lo = g_wk_lo; j = i - NW; }
        else                 { src = wv; hi = g_wv_hi; lo = g_wv_lo; j = i - 2 * NW; }
        float val = src[j];
        f16 h = __float2half_rn(val);
        hi[j] = h;
        lo[j] = __float2half_rn(val - __half2float(h));
    } else {
        long j = i - 3 * NW;
        g_wo[j] = __float2half_rn(wo[j]);
    }
}

// ----------------------------------------------------------------------------
// Row softmax fp32 -> fp16   (n == 2048, 256 threads)
// ----------------------------------------------------------------------------
__global__ void softmax_f16(const float* __restrict__ S, f16* __restrict__ P, int n) {
    const float* row = S + (long)blockIdx.x * n;
    __shared__ float red[256];
    const int t = threadIdx.x;
    float e[8];
    float m = -1e30f;
#pragma unroll
    for (int i = 0; i < 8; i++) { e[i] = row[t + i * 256]; m = fmaxf(m, e[i]); }
    red[t] = m; __syncthreads();
    for (int s = 128; s > 0; s >>= 1) {
        if (t < s) red[t] = fmaxf(red[t], red[t + s]);
        __syncthreads();
    }
    m = red[0]; __syncthreads();
    float sum = 0.f;
#pragma unroll
    for (int i = 0; i < 8; i++) { e[i] = __expf(e[i] - m); sum += e[i]; }
    red[t] = sum; __syncthreads();
    for (int s = 128; s > 0; s >>= 1) {
        if (t < s) red[t] += red[t + s];
        __syncthreads();
    }
    float inv = 1.0f / red[0];
#pragma unroll
    for (int i = 0; i < 8; i++)
        P[(long)blockIdx.x * n + t + i * 256] = __float2half_rn(e[i] * inv);
}

// ----------------------------------------------------------------------------
// mma.sync templated GEMM (NT): C[m,n] = alpha * sum_k A[m,k]*B[n,k] (+bias)
//   PROD==1: A single x B single.
//   PROD==2: A single x (Bh+Bl).
//   PROD==3: (Ah+Al) x (Bh+Bl), Al*Bl dropped.
//   CTA 128x128, BK=32, 2-stage cp.async, 8 warps (64x32 each). R5 skeleton.
//   mode 0: fp32 out.  mode 1: fp16 single out.  mode 2: fp16 pair out.
// ----------------------------------------------------------------------------
#define BM 128
#define BN 128
#define BK 32
#define ROWB 80              // smem row stride bytes (32 fp16 = 64B data + 16B pad)
#define TILEB (128 * ROWB)   // 10240 B per matrix tile

template <int PROD>
__global__ void __launch_bounds__(256) gemmP(
    const f16* __restrict__ Ahi, const f16* __restrict__ Alo,
    const f16* __restrict__ Bhi, const f16* __restrict__ Blo,
    const float* __restrict__ bias,
    float* __restrict__ Cf, f16* __restrict__ C1, f16* __restrict__ C2,
    int N, int K, int ldc, float alpha,
    long sA, long sB, long sC, int mode, int transC)
{
    constexpr int NT = (PROD == 3) ? 4 : (PROD == 2 ? 3 : 2);
    constexpr int OFF_AH = 0;
    constexpr int OFF_AL = TILEB;                        // PROD==3 only
    constexpr int OFF_BH = (PROD == 3) ? 2 * TILEB : TILEB;
    constexpr int OFF_BL = OFF_BH + TILEB;               // PROD>=2 only
    constexpr int STAGE  = NT * TILEB;

    extern __shared__ char smem[];
    const uint32_t sb = smem_u32(smem);
    const int tid = threadIdx.x;
    const int wid = tid >> 5;
    const int lid = tid & 31;
    const int wm = (wid & 1) * 64;       // warp M offset in CTA tile
    const int wn = (wid >> 1) * 32;      // warp N offset
    const long bz = blockIdx.z;
    const int m0 = blockIdx.y * BM;
    const int n0 = blockIdx.x * BN;

    const f16* pAh = Ahi + bz * sA;
    const f16* pAl = (PROD == 3) ? (Alo + bz * sA) : nullptr;
    const f16* pBh = Bhi + bz * sB;
    const f16* pBl = (PROD >= 2) ? (Blo + bz * sB) : nullptr;

    const int lrow = tid >> 2;           // 0..63 base row for loads
    const int lch  = tid & 3;            // 16B chunk 0..3

    float acc[4][4][4];
#pragma unroll
    for (int i = 0; i < 4; ++i)
#pragma unroll
        for (int j = 0; j < 4; ++j)
#pragma unroll
            for (int c = 0; c < 4; ++c) acc[i][j][c] = 0.f;

    const int nch = K / BK;

    // ---- stage loader: 2 rows x NT tiles per thread ----
    auto issue = [&](int ch, int buf) {
        const int k0 = ch * BK;
        const uint32_t s0 = sb + buf * STAGE;
#pragma unroll
        for (int h = 0; h < 2; ++h) {
            const int r = lrow + h * 64;
            const uint32_t so = (uint32_t)(r * ROWB + lch * 16);
            const long goA = (long)(m0 + r) * K + k0 + lch * 8;
            const long goB = (long)(n0 + r) * K + k0 + lch * 8;
            cp16(s0 + OFF_AH + so, pAh + goA);
            if (PROD == 3) cp16(s0 + OFF_AL + so, pAl + goA);
            cp16(s0 + OFF_BH + so, pBh + goB);
            if (PROD >= 2) cp16(s0 + OFF_BL + so, pBl + goB);
        }
    };

    issue(0, 0);
    CP_COMMIT();

    // ldmatrix lane addressing (within a stage buffer)
    const int a_row = lid & 15;                    // 0..15
    const int a_col = (lid >> 4) * 16;             // 0 or 16 bytes
    const int b_nin = ((lid >> 4) & 1) * 8 + (lid & 7);  // n within 16-block
    const int b_col = ((lid >> 3) & 1) * 16;       // k-half bytes

    for (int ch = 0; ch < nch; ++ch) {
        if (ch + 1 < nch) { issue(ch + 1, (ch + 1) & 1); CP_COMMIT(); CP_WAIT(1); }
        else              { CP_WAIT(0); }
        __syncthreads();

        const uint32_t s0 = sb + (ch & 1) * STAGE;

#pragma unroll
        for (int ks = 0; ks < 2; ++ks) {
            const int kb = ks * 32 + a_col;        // A k-byte offset for this lane
            uint32_t af[4][4];
#pragma unroll
            for (int mt = 0; mt < 4; ++mt) {
                const uint32_t ro = (uint32_t)((wm + mt * 16 + a_row) * ROWB);
                ldsm4(af[mt][0], af[mt][1], af[mt][2], af[mt][3], s0 + OFF_AH + ro + kb);
            }
            uint32_t bh[2][4], bl[2][4];
#pragma unroll
            for (int np = 0; np < 2; ++np) {
                const uint32_t ro = (uint32_t)((wn + np * 16 + b_nin) * ROWB + ks * 32 + b_col);
                ldsm4(bh[np][0], bh[np][1], bh[np][2], bh[np][3], s0 + OFF_BH + ro);
                if (PROD >= 2)
                    ldsm4(bl[np][0], bl[np][1], bl[np][2], bl[np][3], s0 + OFF_BL + ro);
            }
            // R5-style interleaved products: per (mt,nt) hh then hl
#pragma unroll
            for (int mt = 0; mt < 4; ++mt) {
#pragma unroll
                for (int nt = 0; nt < 4; ++nt) {
                    const int np = nt >> 1, sel = (nt & 1) * 2;
                    mma16816(acc[mt][nt], af[mt], &bh[np][sel]);
                    if (PROD >= 2)
                        mma16816(acc[mt][nt], af[mt], &bl[np][sel]);
                }
            }
            // PROD==3: lazy A-lo pass (4-reg live range): per mt, al x bh
            if (PROD == 3) {
#pragma unroll
                for (int mt = 0; mt < 4; ++mt) {
                    uint32_t al[4];
                    const uint32_t ro = (uint32_t)((wm + mt * 16 + a_row) * ROWB);
                    ldsm4(al[0], al[1], al[2], al[3], s0 + OFF_AL + ro + kb);
#pragma unroll
                    for (int nt = 0; nt < 4; ++nt) {
                        const int np = nt >> 1, sel = (nt & 1) * 2;
                        mma16816(acc[mt][nt], al, &bh[np][sel]);
                    }
                }
            }
        }
        __syncthreads();
    }

    // ---- epilogue ----
    const int gr = lid >> 2;             // group row 0..7
    const int tg = lid & 3;              // col pair 0..3
#pragma unroll
    for (int mt = 0; mt < 4; ++mt) {
#pragma unroll
        for (int nt = 0; nt < 4; ++nt) {
#pragma unroll
            for (int h = 0; h < 2; ++h) {        // c0c1 vs c2c3 (row +8)
                const int m = m0 + wm + mt * 16 + gr + h * 8;
#pragma unroll
                for (int c = 0; c < 2; ++c) {
                    const int n = n0 + wn + nt * 8 + tg * 2 + c;
                    float v = acc[mt][nt][h * 2 + c] * alpha;
                    if (bias) v += __ldg(bias + n);
                    if (mode == 0) {
                        Cf[bz * sC + (long)m * ldc + n] = v;
                    } else {
                        long o = transC ? (bz * sC + (long)n * ldc + m)
                                        : (bz * sC + (long)m * ldc + n);
                        f16 hh = __float2half_rn(v);
                        C1[o] = hh;
                        if (mode == 2)
                            C2[o] = __float2half_rn(v - __half2float(hh));
                    }
                }
            }
        }
    }
}

#define SMEM1 (2 * 2 * TILEB)   // 40960
#define SMEM2 (2 * 3 * TILEB)   // 61440
#define SMEM3 (2 * 4 * TILEB)   // 81920

// ----------------------------------------------------------------------------
// launch
// ----------------------------------------------------------------------------
extern "C" void kernel_launch(void* const* d_in, const int* in_sizes, int n_in,
                              void* d_out, int out_size) {
    const float* q  = (const float*)d_in[0];
    const float* k  = (const float*)d_in[1];
    const float* v  = (const float*)d_in[2];
    const float* Wq = (const float*)d_in[3];
    const float* bq = (const float*)d_in[4];
    const float* Wk = (const float*)d_in[5];
    const float* bk = (const float*)d_in[6];
    const float* Wv = (const float*)d_in[7];
    const float* bv = (const float*)d_in[8];
    const float* Wo = (const float*)d_in[9];
    const float* bo = (const float*)d_in[10];
    float* out = (float*)d_out;

    f16 *xqh, *xql, *xkh, *xkl, *xv, *wo, *qp, *at, *av, *vT;
    f16 *wqh, *wql, *wkh, *wkl, *wvh, *wvl, *kph, *kpl;
    float* sc;
    cudaGetSymbolAddress((void**)&xqh, g_xq_hi); cudaGetSymbolAddress((void**)&xql, g_xq_lo);
    cudaGetSymbolAddress((void**)&xkh, g_xk_hi); cudaGetSymbolAddress((void**)&xkl, g_xk_lo);
    cudaGetSymbolAddress((void**)&xv,  g_xv);
    cudaGetSymbolAddress((void**)&wqh, g_wq_hi); cudaGetSymbolAddress((void**)&wql, g_wq_lo);
    cudaGetSymbolAddress((void**)&wkh, g_wk_hi); cudaGetSymbolAddress((void**)&wkl, g_wk_lo);
    cudaGetSymbolAddress((void**)&wvh, g_wv_hi); cudaGetSymbolAddress((void**)&wvl, g_wv_lo);
    cudaGetSymbolAddress((void**)&wo,  g_wo);
    cudaGetSymbolAddress((void**)&qp,  g_qp);
    cudaGetSymbolAddress((void**)&kph, g_kp_hi); cudaGetSymbolAddress((void**)&kpl, g_kp_lo);
    cudaGetSymbolAddress((void**)&vT,  g_vT);
    cudaGetSymbolAddress((void**)&at,  g_at);
    cudaGetSymbolAddress((void**)&av,  g_av);
    cudaGetSymbolAddress((void**)&sc,  g_sc);

    cudaFuncSetAttribute(gemmP<1>, cudaFuncAttributeMaxDynamicSharedMemorySize, SMEM1);
    cudaFuncSetAttribute(gemmP<2>, cudaFuncAttributeMaxDynamicSharedMemorySize, SMEM2);
    cudaFuncSetAttribute(gemmP<3>, cudaFuncAttributeMaxDynamicSharedMemorySize, SMEM3);

    const int D = DMOD, S = SEQ, B = BATCH;
    dim3 blk(256);
    dim3 gp(D / BN, (B * S) / BM, 1);    // (8, 64)
    dim3 gv(D / BN, S / BM, B);          // (8, 16, 4)
    dim3 gs(S / BN, S / BM, B);          // (16, 16, 4)
    dim3 ga(D / BN, S / BM, B);          // (8, 16, 4)

    // 1-2: conversions
    conv_inputs <<<(unsigned)((3 * NQ + 511) / 512), 512>>>(q, k, v);
    conv_weights<<<(unsigned)((4 * NW + 511) / 512), 512>>>(Wq, Wk, Wv, Wo);

    // 3: q projection (3P: xq pair x wq pair) -> qp single
    gemmP<3><<<gp, blk, SMEM3>>>(xqh, xql, wqh, wql, bq, nullptr, qp, nullptr,
                                 D, D, D, 1.0f, 0, 0, 0, 1, 0);
    // 4: k projection (3P) -> kp pair
    gemmP<3><<<gp, blk, SMEM3>>>(xkh, xkl, wkh, wkl, bk, nullptr, kph, kpl,
                                 D, D, D, 1.0f, 0, 0, 0, 2, 0);
    // 5: v projection (2P: xv single x wv pair) -> vT single, transposed [B][D][S]
    gemmP<2><<<gv, blk, SMEM2>>>(xv, nullptr, wvh, wvl, bv, nullptr, vT, nullptr,
                                 D, D, /*ldc=*/S, 1.0f,
                                 (long)S * D, 0, (long)D * S, 1, 1);
    // 6: scores (2P: qp single x kp pair) -> fp32      <-- ncu -s 5 -c 1 capture
    gemmP<2><<<gs, blk, SMEM2>>>(qp, nullptr, kph, kpl, nullptr, sc, nullptr, nullptr,
                                 S, D, S, 0.125f,
                                 (long)S * D, (long)S * D, (long)S * S, 0, 0);
    // 7: softmax -> fp16 probs
    softmax_f16<<<(unsigned)(B * S), 256>>>(sc, at, S);
    // 8: av (1P: at single x vT single) -> av single
    gemmP<1><<<ga, blk, SMEM1>>>(at, nullptr, vT, nullptr, nullptr, nullptr, av, nullptr,
                                 D, S, D, 1.0f,
                                 (long)S * S, (long)D * S, (long)S * D, 1, 0);
    // 9: out (1P: av single x wo single) + bo -> fp32
    gemmP<1><<<gp, blk, SMEM1>>>(av, nullptr, wo, nullptr, bo, out, nullptr, nullptr,
                                 D, D, D, 1.0f, 0, 0, 0, 0, 0);
}

// round 13
// speedup vs baseline: 1.6126x; 1.1040x over previous
#include <cuda_runtime.h>
#include <cuda_fp16.h>
#include <stdint.h>

typedef __half f16;

#define BATCH 4
#define SEQ   2048
#define DMOD  1024

#define NQ ((long)BATCH*SEQ*DMOD)   // 8,388,608
#define NW ((long)DMOD*DMOD)        // 1,048,576
#define NS ((long)BATCH*SEQ*SEQ)    // 16,777,216

// ----------------------------------------------------------------------------
// Scratch (device globals; allocation is forbidden)
// ----------------------------------------------------------------------------
__device__ __align__(256) f16 g_xq_hi[NQ], g_xq_lo[NQ];            // q input, pair
__device__ __align__(256) f16 g_xk_hi[NQ], g_xk_lo[NQ];            // k input, pair
__device__ __align__(256) f16 g_xv[NQ];                            // v input, single
__device__ __align__(256) f16 g_wq_hi[NW], g_wq_lo[NW];
__device__ __align__(256) f16 g_wk_hi[NW], g_wk_lo[NW];
__device__ __align__(256) f16 g_wv_hi[NW], g_wv_lo[NW];
__device__ __align__(256) f16 g_wo[NW];                            // Wo, single
__device__ __align__(256) f16 g_qp[NQ];                            // q-proj, single
__device__ __align__(256) f16 g_kp[NQ];                            // k-proj, single
__device__ __align__(256) f16 g_vT[NQ];                            // v-proj [B][D][S], single
__device__ __align__(256) float g_sc[NS];                          // scores fp32
__device__ __align__(256) f16 g_at[NS];                            // probs, single
__device__ __align__(256) f16 g_av[NQ];                            // attn@V, single

// ----------------------------------------------------------------------------
// helpers
// ----------------------------------------------------------------------------
__device__ __forceinline__ uint32_t smem_u32(const void* p) {
    uint32_t a;
    asm("{ .reg .u64 t; cvta.to.shared.u64 t, %1; cvt.u32.u64 %0, t; }" : "=r"(a) : "l"(p));
    return a;
}
__device__ __forceinline__ void cp16(uint32_t s, const void* g) {
    asm volatile("cp.async.cg.shared.global [%0], [%1], 16;" :: "r"(s), "l"(g));
}
#define CP_COMMIT() asm volatile("cp.async.commit_group;" ::: "memory")
#define CP_WAIT(n)  asm volatile("cp.async.wait_group %0;" :: "n"(n) : "memory")

__device__ __forceinline__ void ldsm4(uint32_t& r0, uint32_t& r1, uint32_t& r2,
                                      uint32_t& r3, uint32_t addr) {
    asm volatile("ldmatrix.sync.aligned.m8n8.x4.shared.b16 {%0,%1,%2,%3}, [%4];"
                 : "=r"(r0), "=r"(r1), "=r"(r2), "=r"(r3) : "r"(addr));
}
__device__ __forceinline__ void mma16816(float* d, const uint32_t* a, const uint32_t* b) {
    asm volatile(
        "mma.sync.aligned.m16n8k16.row.col.f32.f16.f16.f32 "
        "{%0,%1,%2,%3}, {%4,%5,%6,%7}, {%8,%9}, {%0,%1,%2,%3};"
        : "+f"(d[0]), "+f"(d[1]), "+f"(d[2]), "+f"(d[3])
        : "r"(a[0]), "r"(a[1]), "r"(a[2]), "r"(a[3]), "r"(b[0]), "r"(b[1]));
}

// ----------------------------------------------------------------------------
// fused conversions
// ----------------------------------------------------------------------------
// q,k -> fp16 pairs; v -> fp16 single
__global__ void conv_inputs(const float* __restrict__ q, const float* __restrict__ k,
                            const float* __restrict__ v) {
    long i = (long)blockIdx.x * blockDim.x + threadIdx.x;
    if (i >= 3 * NQ) return;
    if (i < NQ) {
        float val = q[i];
        f16 h = __float2half_rn(val);
        g_xq_hi[i] = h;
        g_xq_lo[i] = __float2half_rn(val - __half2float(h));
    } else if (i < 2 * NQ) {
        long j = i - NQ;
        float val = k[j];
        f16 h = __float2half_rn(val);
        g_xk_hi[j] = h;
        g_xk_lo[j] = __float2half_rn(val - __half2float(h));
    } else {
        long j = i - 2 * NQ;
        g_xv[j] = __float2half_rn(v[j]);
    }
}

// Wq,Wk,Wv -> fp16 pairs; Wo -> fp16 single
__global__ void conv_weights(const float* __restrict__ wq, const float* __restrict__ wk,
                             const float* __restrict__ wv, const float* __restrict__ wo) {
    long i = (long)blockIdx.x * blockDim.x + threadIdx.x;
    if (i >= 4 * NW) return;
    if (i < 3 * NW) {
        const float* src; f16 *hi, *lo; long j;
        if (i < NW)          { src = wq; hi = g_wq_hi; lo = g_wq_lo; j = i; }
        else if (i < 2 * NW) { src = wk; hi = g_wk_hi; lo = g_wk_lo; j = i - NW; }
        else                 { src = wv; hi = g_wv_hi; lo = g_wv_lo; j = i - 2 * NW; }
        float val = src[j];
        f16 h = __float2half_rn(val);
        hi[j] = h;
        lo[j] = __float2half_rn(val - __half2float(h));
    } else {
        long j = i - 3 * NW;
        g_wo[j] = __float2half_rn(wo[j]);
    }
}

// ----------------------------------------------------------------------------
// Row softmax fp32 -> fp16   (n == 2048, 256 threads)
// ----------------------------------------------------------------------------
__global__ void softmax_f16(const float* __restrict__ S, f16* __restrict__ P, int n) {
    const float* row = S + (long)blockIdx.x * n;
    __shared__ float red[256];
    const int t = threadIdx.x;
    float e[8];
    float m = -1e30f;
#pragma unroll
    for (int i = 0; i < 8; i++) { e[i] = row[t + i * 256]; m = fmaxf(m, e[i]); }
    red[t] = m; __syncthreads();
    for (int s = 128; s > 0; s >>= 1) {
        if (t < s) red[t] = fmaxf(red[t], red[t + s]);
        __syncthreads();
    }
    m = red[0]; __syncthreads();
    float sum = 0.f;
#pragma unroll
    for (int i = 0; i < 8; i++) { e[i] = __expf(e[i] - m); sum += e[i]; }
    red[t] = sum; __syncthreads();
    for (int s = 128; s > 0; s >>= 1) {
        if (t < s) red[t] += red[t + s];
        __syncthreads();
    }
    float inv = 1.0f / red[0];
#pragma unroll
    for (int i = 0; i < 8; i++)
        P[(long)blockIdx.x * n + t + i * 256] = __float2half_rn(e[i] * inv);
}

// ----------------------------------------------------------------------------
// mma.sync templated GEMM (NT): C[m,n] = alpha * sum_k A[m,k]*B[n,k] (+bias)
//   PROD==1: A single x B single.
//   PROD==2: A single x (Bh+Bl).
//   PROD==3: (Ah+Al) x (Bh+Bl), Al*Bl dropped.
//   CTA 128x128, BK=32, 2-stage cp.async, 8 warps (64x32 each). R5 skeleton.
//   mode 0: fp32 out.  mode 1: fp16 single out.  mode 2: fp16 pair out.
// ----------------------------------------------------------------------------
#define BM 128
#define BN 128
#define BK 32
#define ROWB 80              // smem row stride bytes (32 fp16 = 64B data + 16B pad)
#define TILEB (128 * ROWB)   // 10240 B per matrix tile

template <int PROD>
__global__ void __launch_bounds__(256) gemmP(
    const f16* __restrict__ Ahi, const f16* __restrict__ Alo,
    const f16* __restrict__ Bhi, const f16* __restrict__ Blo,
    const float* __restrict__ bias,
    float* __restrict__ Cf, f16* __restrict__ C1, f16* __restrict__ C2,
    int N, int K, int ldc, float alpha,
    long sA, long sB, long sC, int mode, int transC)
{
    constexpr int NT = (PROD == 3) ? 4 : (PROD == 2 ? 3 : 2);
    constexpr int OFF_AH = 0;
    constexpr int OFF_AL = TILEB;                        // PROD==3 only
    constexpr int OFF_BH = (PROD == 3) ? 2 * TILEB : TILEB;
    constexpr int OFF_BL = OFF_BH + TILEB;               // PROD>=2 only
    constexpr int STAGE  = NT * TILEB;

    extern __shared__ char smem[];
    const uint32_t sb = smem_u32(smem);
    const int tid = threadIdx.x;
    const int wid = tid >> 5;
    const int lid = tid & 31;
    const int wm = (wid & 1) * 64;       // warp M offset in CTA tile
    const int wn = (wid >> 1) * 32;      // warp N offset
    const long bz = blockIdx.z;
    const int m0 = blockIdx.y * BM;
    const int n0 = blockIdx.x * BN;

    const f16* pAh = Ahi + bz * sA;
    const f16* pAl = (PROD == 3) ? (Alo + bz * sA) : nullptr;
    const f16* pBh = Bhi + bz * sB;
    const f16* pBl = (PROD >= 2) ? (Blo + bz * sB) : nullptr;

    const int lrow = tid >> 2;           // 0..63 base row for loads
    const int lch  = tid & 3;            // 16B chunk 0..3

    float acc[4][4][4];
#pragma unroll
    for (int i = 0; i < 4; ++i)
#pragma unroll
        for (int j = 0; j < 4; ++j)
#pragma unroll
            for (int c = 0; c < 4; ++c) acc[i][j][c] = 0.f;

    const int nch = K / BK;

    // ---- stage loader: 2 rows x NT tiles per thread ----
    auto issue = [&](int ch, int buf) {
        const int k0 = ch * BK;
        const uint32_t s0 = sb + buf * STAGE;
#pragma unroll
        for (int h = 0; h < 2; ++h) {
            const int r = lrow + h * 64;
            const uint32_t so = (uint32_t)(r * ROWB + lch * 16);
            const long goA = (long)(m0 + r) * K + k0 + lch * 8;
            const long goB = (long)(n0 + r) * K + k0 + lch * 8;
            cp16(s0 + OFF_AH + so, pAh + goA);
            if (PROD == 3) cp16(s0 + OFF_AL + so, pAl + goA);
            cp16(s0 + OFF_BH + so, pBh + goB);
            if (PROD >= 2) cp16(s0 + OFF_BL + so, pBl + goB);
        }
    };

    issue(0, 0);
    CP_COMMIT();

    // ldmatrix lane addressing (within a stage buffer)
    const int a_row = lid & 15;                    // 0..15
    const int a_col = (lid >> 4) * 16;             // 0 or 16 bytes
    const int b_nin = ((lid >> 4) & 1) * 8 + (lid & 7);  // n within 16-block
    const int b_col = ((lid >> 3) & 1) * 16;       // k-half bytes

    for (int ch = 0; ch < nch; ++ch) {
        if (ch + 1 < nch) { issue(ch + 1, (ch + 1) & 1); CP_COMMIT(); CP_WAIT(1); }
        else              { CP_WAIT(0); }
        __syncthreads();

        const uint32_t s0 = sb + (ch & 1) * STAGE;

#pragma unroll
        for (int ks = 0; ks < 2; ++ks) {
            const int kb = ks * 32 + a_col;        // A k-byte offset for this lane
            uint32_t af[4][4];
#pragma unroll
            for (int mt = 0; mt < 4; ++mt) {
                const uint32_t ro = (uint32_t)((wm + mt * 16 + a_row) * ROWB);
                ldsm4(af[mt][0], af[mt][1], af[mt][2], af[mt][3], s0 + OFF_AH + ro + kb);
            }
            uint32_t bh[2][4], bl[2][4];
#pragma unroll
            for (int np = 0; np < 2; ++np) {
                const uint32_t ro = (uint32_t)((wn + np * 16 + b_nin) * ROWB + ks * 32 + b_col);
                ldsm4(bh[np][0], bh[np][1], bh[np][2], bh[np][3], s0 + OFF_BH + ro);
                if (PROD >= 2)
                    ldsm4(bl[np][0], bl[np][1], bl[np][2], bl[np][3], s0 + OFF_BL + ro);
            }
            // R5-style interleaved products: per (mt,nt) hh then hl
#pragma unroll
            for (int mt = 0; mt < 4; ++mt) {
#pragma unroll
                for (int nt = 0; nt < 4; ++nt) {
                    const int np = nt >> 1, sel = (nt & 1) * 2;
                    mma16816(acc[mt][nt], af[mt], &bh[np][sel]);
                    if (PROD >= 2)
                        mma16816(acc[mt][nt], af[mt], &bl[np][sel]);
                }
            }
            // PROD==3: lazy A-lo pass (4-reg live range): per mt, al x bh
            if (PROD == 3) {
#pragma unroll
                for (int mt = 0; mt < 4; ++mt) {
                    uint32_t al[4];
                    const uint32_t ro = (uint32_t)((wm + mt * 16 + a_row) * ROWB);
                    ldsm4(al[0], al[1], al[2], al[3], s0 + OFF_AL + ro + kb);
#pragma unroll
                    for (int nt = 0; nt < 4; ++nt) {
                        const int np = nt >> 1, sel = (nt & 1) * 2;
                        mma16816(acc[mt][nt], al, &bh[np][sel]);
                    }
                }
            }
        }
        __syncthreads();
    }

    // ---- epilogue ----
    const int gr = lid >> 2;             // group row 0..7
    const int tg = lid & 3;              // col pair 0..3
#pragma unroll
    for (int mt = 0; mt < 4; ++mt) {
#pragma unroll
        for (int nt = 0; nt < 4; ++nt) {
#pragma unroll
            for (int h = 0; h < 2; ++h) {        // c0c1 vs c2c3 (row +8)
                const int m = m0 + wm + mt * 16 + gr + h * 8;
#pragma unroll
                for (int c = 0; c < 2; ++c) {
                    const int n = n0 + wn + nt * 8 + tg * 2 + c;
                    float v = acc[mt][nt][h * 2 + c] * alpha;
                    if (bias) v += __ldg(bias + n);
                    if (mode == 0) {
                        Cf[bz * sC + (long)m * ldc + n] = v;
                    } else {
                        long o = transC ? (bz * sC + (long)n * ldc + m)
                                        : (bz * sC + (long)m * ldc + n);
                        f16 hh = __float2half_rn(v);
                        C1[o] = hh;
                        if (mode == 2)
                            C2[o] = __float2half_rn(v - __half2float(hh));
                    }
                }
            }
        }
    }
}

#define SMEM1 (2 * 2 * TILEB)   // 40960
#define SMEM2 (2 * 3 * TILEB)   // 61440
#define SMEM3 (2 * 4 * TILEB)   // 81920

// ----------------------------------------------------------------------------
// launch
// ----------------------------------------------------------------------------
extern "C" void kernel_launch(void* const* d_in, const int* in_sizes, int n_in,
                              void* d_out, int out_size) {
    const float* q  = (const float*)d_in[0];
    const float* k  = (const float*)d_in[1];
    const float* v  = (const float*)d_in[2];
    const float* Wq = (const float*)d_in[3];
    const float* bq = (const float*)d_in[4];
    const float* Wk = (const float*)d_in[5];
    const float* bk = (const float*)d_in[6];
    const float* Wv = (const float*)d_in[7];
    const float* bv = (const float*)d_in[8];
    const float* Wo = (const float*)d_in[9];
    const float* bo = (const float*)d_in[10];
    float* out = (float*)d_out;

    f16 *xqh, *xql, *xkh, *xkl, *xv, *wo, *qp, *kp, *at, *av, *vT;
    f16 *wqh, *wql, *wkh, *wkl, *wvh, *wvl;
    float* sc;
    cudaGetSymbolAddress((void**)&xqh, g_xq_hi); cudaGetSymbolAddress((void**)&xql, g_xq_lo);
    cudaGetSymbolAddress((void**)&xkh, g_xk_hi); cudaGetSymbolAddress((void**)&xkl, g_xk_lo);
    cudaGetSymbolAddress((void**)&xv,  g_xv);
    cudaGetSymbolAddress((void**)&wqh, g_wq_hi); cudaGetSymbolAddress((void**)&wql, g_wq_lo);
    cudaGetSymbolAddress((void**)&wkh, g_wk_hi); cudaGetSymbolAddress((void**)&wkl, g_wk_lo);
    cudaGetSymbolAddress((void**)&wvh, g_wv_hi); cudaGetSymbolAddress((void**)&wvl, g_wv_lo);
    cudaGetSymbolAddress((void**)&wo,  g_wo);
    cudaGetSymbolAddress((void**)&qp,  g_qp);
    cudaGetSymbolAddress((void**)&kp,  g_kp);
    cudaGetSymbolAddress((void**)&vT,  g_vT);
    cudaGetSymbolAddress((void**)&at,  g_at);
    cudaGetSymbolAddress((void**)&av,  g_av);
    cudaGetSymbolAddress((void**)&sc,  g_sc);

    cudaFuncSetAttribute(gemmP<1>, cudaFuncAttributeMaxDynamicSharedMemorySize, SMEM1);
    cudaFuncSetAttribute(gemmP<2>, cudaFuncAttributeMaxDynamicSharedMemorySize, SMEM2);
    cudaFuncSetAttribute(gemmP<3>, cudaFuncAttributeMaxDynamicSharedMemorySize, SMEM3);

    const int D = DMOD, S = SEQ, B = BATCH;
    dim3 blk(256);
    dim3 gp(D / BN, (B * S) / BM, 1);    // (8, 64)
    dim3 gv(D / BN, S / BM, B);          // (8, 16, 4)
    dim3 gs(S / BN, S / BM, B);          // (16, 16, 4)
    dim3 ga(D / BN, S / BM, B);          // (8, 16, 4)

    // 1-2: conversions
    conv_inputs <<<(unsigned)((3 * NQ + 511) / 512), 512>>>(q, k, v);
    conv_weights<<<(unsigned)((4 * NW + 511) / 512), 512>>>(Wq, Wk, Wv, Wo);

    // 3: q projection (3P: xq pair x wq pair) -> qp single
    gemmP<3><<<gp, blk, SMEM3>>>(xqh, xql, wqh, wql, bq, nullptr, qp, nullptr,
                                 D, D, D, 1.0f, 0, 0, 0, 1, 0);
    // 4: k projection (3P) -> kp single
    gemmP<3><<<gp, blk, SMEM3>>>(xkh, xkl, wkh, wkl, bk, nullptr, kp, nullptr,
                                 D, D, D, 1.0f, 0, 0, 0, 1, 0);
    // 5: v projection (2P: xv single x wv pair) -> vT single, transposed [B][D][S]
    gemmP<2><<<gv, blk, SMEM2>>>(xv, nullptr, wvh, wvl, bv, nullptr, vT, nullptr,
                                 D, D, /*ldc=*/S, 1.0f,
                                 (long)S * D, 0, (long)D * S, 1, 1);
    // 6: scores (1P: qp single x kp single) -> fp32    <-- ncu -s 5 -c 1 capture
    gemmP<1><<<gs, blk, SMEM1>>>(qp, nullptr, kp, nullptr, nullptr, sc, nullptr, nullptr,
                                 S, D, S, 0.125f,
                                 (long)S * D, (long)S * D, (long)S * S, 0, 0);
    // 7: softmax -> fp16 probs
    softmax_f16<<<(unsigned)(B * S), 256>>>(sc, at, S);
    // 8: av (1P: at single x vT single) -> av single
    gemmP<1><<<ga, blk, SMEM1>>>(at, nullptr, vT, nullptr, nullptr, nullptr, av, nullptr,
                                 D, S, D, 1.0f,
                                 (long)S * S, (long)D * S, (long)S * D, 1, 0);
    // 9: out (1P: av single x wo single) + bo -> fp32
    gemmP<1><<<gp, blk, SMEM1>>>(av, nullptr, wo, nullptr, bo, out, nullptr, nullptr,
                                 D, D, D, 1.0f, 0, 0, 0, 0, 0);
}

// round 14
// speedup vs baseline: 1.6970x; 1.0524x over previous
#include <cuda_runtime.h>
#include <cuda_fp16.h>
#include <stdint.h>

typedef __half f16;

#define BATCH 4
#define SEQ   2048
#define DMOD  1024

#define NQ ((long)BATCH*SEQ*DMOD)   // 8,388,608
#define NW ((long)DMOD*DMOD)        // 1,048,576
#define NS ((long)BATCH*SEQ*SEQ)    // 16,777,216

// ----------------------------------------------------------------------------
// Scratch (device globals; allocation is forbidden)
// ----------------------------------------------------------------------------
__device__ __align__(256) f16 g_xq_hi[NQ], g_xq_lo[NQ];            // q input, pair
__device__ __align__(256) f16 g_xk_hi[NQ], g_xk_lo[NQ];            // k input, pair
__device__ __align__(256) f16 g_xv[NQ];                            // v input, single
__device__ __align__(256) f16 g_wq_hi[NW], g_wq_lo[NW];
__device__ __align__(256) f16 g_wk_hi[NW], g_wk_lo[NW];
__device__ __align__(256) f16 g_wv[NW];                            // Wv, single
__device__ __align__(256) f16 g_wo[NW];                            // Wo, single
__device__ __align__(256) f16 g_qp[NQ];                            // q-proj, single
__device__ __align__(256) f16 g_kp[NQ];                            // k-proj, single
__device__ __align__(256) f16 g_vT[NQ];                            // v-proj [B][D][S], single
__device__ __align__(256) float g_sc[NS];                          // scores fp32
__device__ __align__(256) f16 g_at[NS];                            // probs, single
__device__ __align__(256) f16 g_av[NQ];                            // attn@V, single

// ----------------------------------------------------------------------------
// helpers
// ----------------------------------------------------------------------------
__device__ __forceinline__ uint32_t smem_u32(const void* p) {
    uint32_t a;
    asm("{ .reg .u64 t; cvta.to.shared.u64 t, %1; cvt.u32.u64 %0, t; }" : "=r"(a) : "l"(p));
    return a;
}
__device__ __forceinline__ void cp16(uint32_t s, const void* g) {
    asm volatile("cp.async.cg.shared.global [%0], [%1], 16;" :: "r"(s), "l"(g));
}
#define CP_COMMIT() asm volatile("cp.async.commit_group;" ::: "memory")
#define CP_WAIT(n)  asm volatile("cp.async.wait_group %0;" :: "n"(n) : "memory")

__device__ __forceinline__ void ldsm4(uint32_t& r0, uint32_t& r1, uint32_t& r2,
                                      uint32_t& r3, uint32_t addr) {
    asm volatile("ldmatrix.sync.aligned.m8n8.x4.shared.b16 {%0,%1,%2,%3}, [%4];"
                 : "=r"(r0), "=r"(r1), "=r"(r2), "=r"(r3) : "r"(addr));
}
__device__ __forceinline__ void mma16816(float* d, const uint32_t* a, const uint32_t* b) {
    asm volatile(
        "mma.sync.aligned.m16n8k16.row.col.f32.f16.f16.f32 "
        "{%0,%1,%2,%3}, {%4,%5,%6,%7}, {%8,%9}, {%0,%1,%2,%3};"
        : "+f"(d[0]), "+f"(d[1]), "+f"(d[2]), "+f"(d[3])
        : "r"(a[0]), "r"(a[1]), "r"(a[2]), "r"(a[3]), "r"(b[0]), "r"(b[1]));
}

// ----------------------------------------------------------------------------
// fused conversions
// ----------------------------------------------------------------------------
// q,k -> fp16 pairs; v -> fp16 single
__global__ void conv_inputs(const float* __restrict__ q, const float* __restrict__ k,
                            const float* __restrict__ v) {
    long i = (long)blockIdx.x * blockDim.x + threadIdx.x;
    if (i >= 3 * NQ) return;
    if (i < NQ) {
        float val = q[i];
        f16 h = __float2half_rn(val);
        g_xq_hi[i] = h;
        g_xq_lo[i] = __float2half_rn(val - __half2float(h));
    } else if (i < 2 * NQ) {
        long j = i - NQ;
        float val = k[j];
        f16 h = __float2half_rn(val);
        g_xk_hi[j] = h;
        g_xk_lo[j] = __float2half_rn(val - __half2float(h));
    } else {
        long j = i - 2 * NQ;
        g_xv[j] = __float2half_rn(v[j]);
    }
}

// Wq,Wk -> fp16 pairs; Wv,Wo -> fp16 single
__global__ void conv_weights(const float* __restrict__ wq, const float* __restrict__ wk,
                             const float* __restrict__ wv, const float* __restrict__ wo) {
    long i = (long)blockIdx.x * blockDim.x + threadIdx.x;
    if (i >= 4 * NW) return;
    if (i < 2 * NW) {
        const float* src; f16 *hi, *lo; long j;
        if (i < NW) { src = wq; hi = g_wq_hi; lo = g_wq_lo; j = i; }
        else        { src = wk; hi = g_wk_hi; lo = g_wk_lo; j = i - NW; }
        float val = src[j];
        f16 h = __float2half_rn(val);
        hi[j] = h;
        lo[j] = __float2half_rn(val - __half2float(h));
    } else if (i < 3 * NW) {
        long j = i - 2 * NW;
        g_wv[j] = __float2half_rn(wv[j]);
    } else {
        long j = i - 3 * NW;
        g_wo[j] = __float2half_rn(wo[j]);
    }
}

// ----------------------------------------------------------------------------
// Row softmax fp32 -> fp16   (n == 2048, 256 threads)
// ----------------------------------------------------------------------------
__global__ void softmax_f16(const float* __restrict__ S, f16* __restrict__ P, int n) {
    const float* row = S + (long)blockIdx.x * n;
    __shared__ float red[256];
    const int t = threadIdx.x;
    float e[8];
    float m = -1e30f;
#pragma unroll
    for (int i = 0; i < 8; i++) { e[i] = row[t + i * 256]; m = fmaxf(m, e[i]); }
    red[t] = m; __syncthreads();
    for (int s = 128; s > 0; s >>= 1) {
        if (t < s) red[t] = fmaxf(red[t], red[t + s]);
        __syncthreads();
    }
    m = red[0]; __syncthreads();
    float sum = 0.f;
#pragma unroll
    for (int i = 0; i < 8; i++) { e[i] = __expf(e[i] - m); sum += e[i]; }
    red[t] = sum; __syncthreads();
    for (int s = 128; s > 0; s >>= 1) {
        if (t < s) red[t] += red[t + s];
        __syncthreads();
    }
    float inv = 1.0f / red[0];
#pragma unroll
    for (int i = 0; i < 8; i++)
        P[(long)blockIdx.x * n + t + i * 256] = __float2half_rn(e[i] * inv);
}

// ----------------------------------------------------------------------------
// mma.sync templated GEMM (NT): C[m,n] = alpha * sum_k A[m,k]*B[n,k] (+bias)
//   PROD==1: A single x B single.
//   PROD==2: A single x (Bh+Bl).
//   PROD==3: (Ah+Al) x (Bh+Bl), Al*Bl dropped.
//   CTA 128x128, BK=32, 2-stage cp.async, 8 warps (64x32 each). R5 skeleton.
//   mode 0: fp32 out.  mode 1: fp16 single out.  mode 2: fp16 pair out.
// ----------------------------------------------------------------------------
#define BM 128
#define BN 128
#define BK 32
#define ROWB 80              // smem row stride bytes (32 fp16 = 64B data + 16B pad)
#define TILEB (128 * ROWB)   // 10240 B per matrix tile

template <int PROD>
__global__ void __launch_bounds__(256) gemmP(
    const f16* __restrict__ Ahi, const f16* __restrict__ Alo,
    const f16* __restrict__ Bhi, const f16* __restrict__ Blo,
    const float* __restrict__ bias,
    float* __restrict__ Cf, f16* __restrict__ C1, f16* __restrict__ C2,
    int N, int K, int ldc, float alpha,
    long sA, long sB, long sC, int mode, int transC)
{
    constexpr int NT = (PROD == 3) ? 4 : (PROD == 2 ? 3 : 2);
    constexpr int OFF_AH = 0;
    constexpr int OFF_AL = TILEB;                        // PROD==3 only
    constexpr int OFF_BH = (PROD == 3) ? 2 * TILEB : TILEB;
    constexpr int OFF_BL = OFF_BH + TILEB;               // PROD>=2 only
    constexpr int STAGE  = NT * TILEB;

    extern __shared__ char smem[];
    const uint32_t sb = smem_u32(smem);
    const int tid = threadIdx.x;
    const int wid = tid >> 5;
    const int lid = tid & 31;
    const int wm = (wid & 1) * 64;       // warp M offset in CTA tile
    const int wn = (wid >> 1) * 32;      // warp N offset
    const long bz = blockIdx.z;
    const int m0 = blockIdx.y * BM;
    const int n0 = blockIdx.x * BN;

    const f16* pAh = Ahi + bz * sA;
    const f16* pAl = (PROD == 3) ? (Alo + bz * sA) : nullptr;
    const f16* pBh = Bhi + bz * sB;
    const f16* pBl = (PROD >= 2) ? (Blo + bz * sB) : nullptr;

    const int lrow = tid >> 2;           // 0..63 base row for loads
    const int lch  = tid & 3;            // 16B chunk 0..3

    float acc[4][4][4];
#pragma unroll
    for (int i = 0; i < 4; ++i)
#pragma unroll
        for (int j = 0; j < 4; ++j)
#pragma unroll
            for (int c = 0; c < 4; ++c) acc[i][j][c] = 0.f;

    const int nch = K / BK;

    // ---- stage loader: 2 rows x NT tiles per thread ----
    auto issue = [&](int ch, int buf) {
        const int k0 = ch * BK;
        const uint32_t s0 = sb + buf * STAGE;
#pragma unroll
        for (int h = 0; h < 2; ++h) {
            const int r = lrow + h * 64;
            const uint32_t so = (uint32_t)(r * ROWB + lch * 16);
            const long goA = (long)(m0 + r) * K + k0 + lch * 8;
            const long goB = (long)(n0 + r) * K + k0 + lch * 8;
            cp16(s0 + OFF_AH + so, pAh + goA);
            if (PROD == 3) cp16(s0 + OFF_AL + so, pAl + goA);
            cp16(s0 + OFF_BH + so, pBh + goB);
            if (PROD >= 2) cp16(s0 + OFF_BL + so, pBl + goB);
        }
    };

    issue(0, 0);
    CP_COMMIT();

    // ldmatrix lane addressing (within a stage buffer)
    const int a_row = lid & 15;                    // 0..15
    const int a_col = (lid >> 4) * 16;             // 0 or 16 bytes
    const int b_nin = ((lid >> 4) & 1) * 8 + (lid & 7);  // n within 16-block
    const int b_col = ((lid >> 3) & 1) * 16;       // k-half bytes

    for (int ch = 0; ch < nch; ++ch) {
        if (ch + 1 < nch) { issue(ch + 1, (ch + 1) & 1); CP_COMMIT(); CP_WAIT(1); }
        else              { CP_WAIT(0); }
        __syncthreads();

        const uint32_t s0 = sb + (ch & 1) * STAGE;

#pragma unroll
        for (int ks = 0; ks < 2; ++ks) {
            const int kb = ks * 32 + a_col;        // A k-byte offset for this lane
            uint32_t af[4][4];
#pragma unroll
            for (int mt = 0; mt < 4; ++mt) {
                const uint32_t ro = (uint32_t)((wm + mt * 16 + a_row) * ROWB);
                ldsm4(af[mt][0], af[mt][1], af[mt][2], af[mt][3], s0 + OFF_AH + ro + kb);
            }
            uint32_t bh[2][4], bl[2][4];
#pragma unroll
            for (int np = 0; np < 2; ++np) {
                const uint32_t ro = (uint32_t)((wn + np * 16 + b_nin) * ROWB + ks * 32 + b_col);
                ldsm4(bh[np][0], bh[np][1], bh[np][2], bh[np][3], s0 + OFF_BH + ro);
                if (PROD >= 2)
                    ldsm4(bl[np][0], bl[np][1], bl[np][2], bl[np][3], s0 + OFF_BL + ro);
            }
            // R5-style interleaved products: per (mt,nt) hh then hl
#pragma unroll
            for (int mt = 0; mt < 4; ++mt) {
#pragma unroll
                for (int nt = 0; nt < 4; ++nt) {
                    const int np = nt >> 1, sel = (nt & 1) * 2;
                    mma16816(acc[mt][nt], af[mt], &bh[np][sel]);
                    if (PROD >= 2)
                        mma16816(acc[mt][nt], af[mt], &bl[np][sel]);
                }
            }
            // PROD==3: lazy A-lo pass (4-reg live range): per mt, al x bh
            if (PROD == 3) {
#pragma unroll
                for (int mt = 0; mt < 4; ++mt) {
                    uint32_t al[4];
                    const uint32_t ro = (uint32_t)((wm + mt * 16 + a_row) * ROWB);
                    ldsm4(al[0], al[1], al[2], al[3], s0 + OFF_AL + ro + kb);
#pragma unroll
                    for (int nt = 0; nt < 4; ++nt) {
                        const int np = nt >> 1, sel = (nt & 1) * 2;
                        mma16816(acc[mt][nt], al, &bh[np][sel]);
                    }
                }
            }
        }
        __syncthreads();
    }

    // ---- epilogue ----
    const int gr = lid >> 2;             // group row 0..7
    const int tg = lid & 3;              // col pair 0..3
#pragma unroll
    for (int mt = 0; mt < 4; ++mt) {
#pragma unroll
        for (int nt = 0; nt < 4; ++nt) {
#pragma unroll
            for (int h = 0; h < 2; ++h) {        // c0c1 vs c2c3 (row +8)
                const int m = m0 + wm + mt * 16 + gr + h * 8;
#pragma unroll
                for (int c = 0; c < 2; ++c) {
                    const int n = n0 + wn + nt * 8 + tg * 2 + c;
                    float v = acc[mt][nt][h * 2 + c] * alpha;
                    if (bias) v += __ldg(bias + n);
                    if (mode == 0) {
                        Cf[bz * sC + (long)m * ldc + n] = v;
                    } else {
                        long o = transC ? (bz * sC + (long)n * ldc + m)
                                        : (bz * sC + (long)m * ldc + n);
                        f16 hh = __float2half_rn(v);
                        C1[o] = hh;
                        if (mode == 2)
                            C2[o] = __float2half_rn(v - __half2float(hh));
                    }
                }
            }
        }
    }
}

#define SMEM1 (2 * 2 * TILEB)   // 40960
#define SMEM2 (2 * 3 * TILEB)   // 61440
#define SMEM3 (2 * 4 * TILEB)   // 81920

// ----------------------------------------------------------------------------
// launch
// ----------------------------------------------------------------------------
extern "C" void kernel_launch(void* const* d_in, const int* in_sizes, int n_in,
                              void* d_out, int out_size) {
    const float* q  = (const float*)d_in[0];
    const float* k  = (const float*)d_in[1];
    const float* v  = (const float*)d_in[2];
    const float* Wq = (const float*)d_in[3];
    const float* bq = (const float*)d_in[4];
    const float* Wk = (const float*)d_in[5];
    const float* bk = (const float*)d_in[6];
    const float* Wv = (const float*)d_in[7];
    const float* bv = (const float*)d_in[8];
    const float* Wo = (const float*)d_in[9];
    const float* bo = (const float*)d_in[10];
    float* out = (float*)d_out;

    f16 *xqh, *xql, *xkh, *xkl, *xv, *wv, *wo, *qp, *kp, *at, *av, *vT;
    f16 *wqh, *wql, *wkh, *wkl;
    float* sc;
    cudaGetSymbolAddress((void**)&xqh, g_xq_hi); cudaGetSymbolAddress((void**)&xql, g_xq_lo);
    cudaGetSymbolAddress((void**)&xkh, g_xk_hi); cudaGetSymbolAddress((void**)&xkl, g_xk_lo);
    cudaGetSymbolAddress((void**)&xv,  g_xv);
    cudaGetSymbolAddress((void**)&wqh, g_wq_hi); cudaGetSymbolAddress((void**)&wql, g_wq_lo);
    cudaGetSymbolAddress((void**)&wkh, g_wk_hi); cudaGetSymbolAddress((void**)&wkl, g_wk_lo);
    cudaGetSymbolAddress((void**)&wv,  g_wv);
    cudaGetSymbolAddress((void**)&wo,  g_wo);
    cudaGetSymbolAddress((void**)&qp,  g_qp);
    cudaGetSymbolAddress((void**)&kp,  g_kp);
    cudaGetSymbolAddress((void**)&vT,  g_vT);
    cudaGetSymbolAddress((void**)&at,  g_at);
    cudaGetSymbolAddress((void**)&av,  g_av);
    cudaGetSymbolAddress((void**)&sc,  g_sc);

    cudaFuncSetAttribute(gemmP<1>, cudaFuncAttributeMaxDynamicSharedMemorySize, SMEM1);
    cudaFuncSetAttribute(gemmP<2>, cudaFuncAttributeMaxDynamicSharedMemorySize, SMEM2);
    cudaFuncSetAttribute(gemmP<3>, cudaFuncAttributeMaxDynamicSharedMemorySize, SMEM3);

    const int D = DMOD, S = SEQ, B = BATCH;
    dim3 blk(256);
    dim3 gp(D / BN, (B * S) / BM, 1);    // (8, 64)
    dim3 gv(D / BN, S / BM, B);          // (8, 16, 4)
    dim3 gs(S / BN, S / BM, B);          // (16, 16, 4)
    dim3 ga(D / BN, S / BM, B);          // (8, 16, 4)

    // 1-2: conversions
    conv_inputs <<<(unsigned)((3 * NQ + 511) / 512), 512>>>(q, k, v);
    conv_weights<<<(unsigned)((4 * NW + 511) / 512), 512>>>(Wq, Wk, Wv, Wo);

    // 3: q projection (3P: xq pair x wq pair) -> qp single
    gemmP<3><<<gp, blk, SMEM3>>>(xqh, xql, wqh, wql, bq, nullptr, qp, nullptr,
                                 D, D, D, 1.0f, 0, 0, 0, 1, 0);
    // 4: k projection (3P) -> kp single
    gemmP<3><<<gp, blk, SMEM3>>>(xkh, xkl, wkh, wkl, bk, nullptr, kp, nullptr,
                                 D, D, D, 1.0f, 0, 0, 0, 1, 0);
    // 5: v projection (1P: xv single x wv single) -> vT single, transposed [B][D][S]
    gemmP<1><<<gv, blk, SMEM1>>>(xv, nullptr, wv, nullptr, bv, nullptr, vT, nullptr,
                                 D, D, /*ldc=*/S, 1.0f,
                                 (long)S * D, 0, (long)D * S, 1, 1);
    // 6: scores (1P: qp single x kp single) -> fp32    <-- ncu -s 5 -c 1 capture
    gemmP<1><<<gs, blk, SMEM1>>>(qp, nullptr, kp, nullptr, nullptr, sc, nullptr, nullptr,
                                 S, D, S, 0.125f,
                                 (long)S * D, (long)S * D, (long)S * S, 0, 0);
    // 7: softmax -> fp16 probs
    softmax_f16<<<(unsigned)(B * S), 256>>>(sc, at, S);
    // 8: av (1P: at single x vT single) -> av single
    gemmP<1><<<ga, blk, SMEM1>>>(at, nullptr, vT, nullptr, nullptr, nullptr, av, nullptr,
                                 D, S, D, 1.0f,
                                 (long)S * S, (long)D * S, (long)S * D, 1, 0);
    // 9: out (1P: av single x wo single) + bo -> fp32
    gemmP<1><<<gp, blk, SMEM1>>>(av, nullptr, wo, nullptr, bo, out, nullptr, nullptr,
                                 D, D, D, 1.0f, 0, 0, 0, 0, 0);
}

// round 15
// speedup vs baseline: 1.8201x; 1.0725x over previous
#include <cuda_runtime.h>
#include <cuda_fp16.h>
#include <stdint.h>

typedef __half f16;

#define BATCH 4
#define SEQ   2048
#define DMOD  1024

#define NQ ((long)BATCH*SEQ*DMOD)   // 8,388,608
#define NW ((long)DMOD*DMOD)        // 1,048,576
#define NS ((long)BATCH*SEQ*SEQ)    // 16,777,216

// ----------------------------------------------------------------------------
// Scratch (device globals; allocation is forbidden)
// ----------------------------------------------------------------------------
__device__ __align__(256) f16 g_xq_hi[NQ], g_xq_lo[NQ];            // q input, pair
__device__ __align__(256) f16 g_xk_hi[NQ], g_xk_lo[NQ];            // k input, pair
__device__ __align__(256) f16 g_xv[NQ];                            // v input, single
__device__ __align__(256) f16 g_wq_hi[NW], g_wq_lo[NW];
__device__ __align__(256) f16 g_wk_hi[NW], g_wk_lo[NW];
__device__ __align__(256) f16 g_wv[NW];                            // Wv, single
__device__ __align__(256) f16 g_wo[NW];                            // Wo, single
__device__ __align__(256) f16 g_qp[NQ];                            // q-proj, single
__device__ __align__(256) f16 g_kp[NQ];                            // k-proj, single
__device__ __align__(256) f16 g_vT[NQ];                            // v-proj [B][D][S], single
__device__ __align__(256) float g_sc[NS];                          // scores fp32
__device__ __align__(256) f16 g_at[NS];                            // probs, single
__device__ __align__(256) f16 g_av[NQ];                            // attn@V, single

// ----------------------------------------------------------------------------
// helpers
// ----------------------------------------------------------------------------
__device__ __forceinline__ uint32_t smem_u32(const void* p) {
    uint32_t a;
    asm("{ .reg .u64 t; cvta.to.shared.u64 t, %1; cvt.u32.u64 %0, t; }" : "=r"(a) : "l"(p));
    return a;
}
__device__ __forceinline__ void cp16(uint32_t s, const void* g) {
    asm volatile("cp.async.cg.shared.global [%0], [%1], 16;" :: "r"(s), "l"(g));
}
#define CP_COMMIT() asm volatile("cp.async.commit_group;" ::: "memory")
#define CP_WAIT(n)  asm volatile("cp.async.wait_group %0;" :: "n"(n) : "memory")

__device__ __forceinline__ void ldsm4(uint32_t& r0, uint32_t& r1, uint32_t& r2,
                                      uint32_t& r3, uint32_t addr) {
    asm volatile("ldmatrix.sync.aligned.m8n8.x4.shared.b16 {%0,%1,%2,%3}, [%4];"
                 : "=r"(r0), "=r"(r1), "=r"(r2), "=r"(r3) : "r"(addr));
}
__device__ __forceinline__ void mma16816(float* d, const uint32_t* a, const uint32_t* b) {
    asm volatile(
        "mma.sync.aligned.m16n8k16.row.col.f32.f16.f16.f32 "
        "{%0,%1,%2,%3}, {%4,%5,%6,%7}, {%8,%9}, {%0,%1,%2,%3};"
        : "+f"(d[0]), "+f"(d[1]), "+f"(d[2]), "+f"(d[3])
        : "r"(a[0]), "r"(a[1]), "r"(a[2]), "r"(a[3]), "r"(b[0]), "r"(b[1]));
}

// ----------------------------------------------------------------------------
// fused conversions (inputs + weights in one launch)
// ----------------------------------------------------------------------------
__global__ void conv_all(const float* __restrict__ q, const float* __restrict__ k,
                         const float* __restrict__ v,
                         const float* __restrict__ wq, const float* __restrict__ wk,
                         const float* __restrict__ wv, const float* __restrict__ wo) {
    long i = (long)blockIdx.x * blockDim.x + threadIdx.x;
    if (i < 3 * NQ) {
        if (i < NQ) {
            float val = q[i];
            f16 h = __float2half_rn(val);
            g_xq_hi[i] = h;
            g_xq_lo[i] = __float2half_rn(val - __half2float(h));
        } else if (i < 2 * NQ) {
            long j = i - NQ;
            float val = k[j];
            f16 h = __float2half_rn(val);
            g_xk_hi[j] = h;
            g_xk_lo[j] = __float2half_rn(val - __half2float(h));
        } else {
            long j = i - 2 * NQ;
            g_xv[j] = __float2half_rn(v[j]);
        }
        return;
    }
    long w = i - 3 * NQ;
    if (w >= 4 * NW) return;
    if (w < 2 * NW) {
        const float* src; f16 *hi, *lo; long j;
        if (w < NW) { src = wq; hi = g_wq_hi; lo = g_wq_lo; j = w; }
        else        { src = wk; hi = g_wk_hi; lo = g_wk_lo; j = w - NW; }
        float val = src[j];
        f16 h = __float2half_rn(val);
        hi[j] = h;
        lo[j] = __float2half_rn(val - __half2float(h));
    } else if (w < 3 * NW) {
        long j = w - 2 * NW;
        g_wv[j] = __float2half_rn(wv[j]);
    } else {
        long j = w - 3 * NW;
        g_wo[j] = __float2half_rn(wo[j]);
    }
}

// ----------------------------------------------------------------------------
// Row softmax fp32 -> fp16   (n == 2048, 256 threads)
// ----------------------------------------------------------------------------
__global__ void softmax_f16(const float* __restrict__ S, f16* __restrict__ P, int n) {
    const float* row = S + (long)blockIdx.x * n;
    __shared__ float red[256];
    const int t = threadIdx.x;
    float e[8];
    float m = -1e30f;
#pragma unroll
    for (int i = 0; i < 8; i++) { e[i] = row[t + i * 256]; m = fmaxf(m, e[i]); }
    red[t] = m; __syncthreads();
    for (int s = 128; s > 0; s >>= 1) {
        if (t < s) red[t] = fmaxf(red[t], red[t + s]);
        __syncthreads();
    }
    m = red[0]; __syncthreads();
    float sum = 0.f;
#pragma unroll
    for (int i = 0; i < 8; i++) { e[i] = __expf(e[i] - m); sum += e[i]; }
    red[t] = sum; __syncthreads();
    for (int s = 128; s > 0; s >>= 1) {
        if (t < s) red[t] += red[t + s];
        __syncthreads();
    }
    float inv = 1.0f / red[0];
#pragma unroll
    for (int i = 0; i < 8; i++)
        P[(long)blockIdx.x * n + t + i * 256] = __float2half_rn(e[i] * inv);
}

// ----------------------------------------------------------------------------
// GEMM geometry (shared by proj_qkv and gemmP)
// ----------------------------------------------------------------------------
#define BM 128
#define BN 128
#define BK 32
#define ROWB 80              // smem row stride bytes (32 fp16 = 64B data + 16B pad)
#define TILEB (128 * ROWB)   // 10240 B per matrix tile
#define SMEM1 (2 * 2 * TILEB)   // 40960
#define SMEM3 (2 * 4 * TILEB)   // 81920

// ----------------------------------------------------------------------------
// Fused QKV projection: grid (8, 64, 3); z=0 q (3P), z=1 k (3P), z=2 v (1P).
// Math identical to the previous per-stage gemmP launches.
// ----------------------------------------------------------------------------
__global__ void __launch_bounds__(256) proj_qkv(
    const float* __restrict__ bq, const float* __restrict__ bk,
    const float* __restrict__ bv)
{
    extern __shared__ char smem[];
    const uint32_t sb = smem_u32(smem);
    const int tid = threadIdx.x;
    const int wid = tid >> 5;
    const int lid = tid & 31;
    const int wm = (wid & 1) * 64;
    const int wn = (wid >> 1) * 32;
    const int z  = blockIdx.z;
    const bool p3 = (z < 2);
    const int m0 = blockIdx.y * BM;
    const int n0 = blockIdx.x * BN;
    const int K = DMOD;

    const f16 *pAh, *pAl, *pBh, *pBl;
    const float* bias;
    if (z == 0)      { pAh = g_xq_hi; pAl = g_xq_lo; pBh = g_wq_hi; pBl = g_wq_lo; bias = bq; }
    else if (z == 1) { pAh = g_xk_hi; pAl = g_xk_lo; pBh = g_wk_hi; pBl = g_wk_lo; bias = bk; }
    else             { pAh = g_xv;    pAl = nullptr;  pBh = g_wv;    pBl = nullptr;  bias = bv; }

    // runtime (CTA-uniform) stage layout
    const uint32_t OFF_BH = p3 ? 2 * TILEB : TILEB;
    const uint32_t STAGE  = p3 ? 4 * TILEB : 2 * TILEB;

    const int lrow = tid >> 2;
    const int lch  = tid & 3;

    float acc[4][4][4];
#pragma unroll
    for (int i = 0; i < 4; ++i)
#pragma unroll
        for (int j = 0; j < 4; ++j)
#pragma unroll
            for (int c = 0; c < 4; ++c) acc[i][j][c] = 0.f;

    const int nch = K / BK;

    auto issue = [&](int ch, int buf) {
        const int k0 = ch * BK;
        const uint32_t s0 = sb + buf * STAGE;
#pragma unroll
        for (int h = 0; h < 2; ++h) {
            const int r = lrow + h * 64;
            const uint32_t so = (uint32_t)(r * ROWB + lch * 16);
            const long goA = (long)(m0 + r) * K + k0 + lch * 8;
            const long goB = (long)(n0 + r) * K + k0 + lch * 8;
            cp16(s0 + so, pAh + goA);
            if (p3) cp16(s0 + TILEB + so, pAl + goA);
            cp16(s0 + OFF_BH + so, pBh + goB);
            if (p3) cp16(s0 + OFF_BH + TILEB + so, pBl + goB);
        }
    };

    issue(0, 0);
    CP_COMMIT();

    const int a_row = lid & 15;
    const int a_col = (lid >> 4) * 16;
    const int b_nin = ((lid >> 4) & 1) * 8 + (lid & 7);
    const int b_col = ((lid >> 3) & 1) * 16;

    for (int ch = 0; ch < nch; ++ch) {
        if (ch + 1 < nch) { issue(ch + 1, (ch + 1) & 1); CP_COMMIT(); CP_WAIT(1); }
        else              { CP_WAIT(0); }
        __syncthreads();

        const uint32_t s0 = sb + (ch & 1) * STAGE;

#pragma unroll
        for (int ks = 0; ks < 2; ++ks) {
            const int kb = ks * 32 + a_col;
            uint32_t af[4][4];
#pragma unroll
            for (int mt = 0; mt < 4; ++mt) {
                const uint32_t ro = (uint32_t)((wm + mt * 16 + a_row) * ROWB);
                ldsm4(af[mt][0], af[mt][1], af[mt][2], af[mt][3], s0 + ro + kb);
            }
            uint32_t bh[2][4], bl[2][4];
#pragma unroll
            for (int np = 0; np < 2; ++np) {
                const uint32_t ro = (uint32_t)((wn + np * 16 + b_nin) * ROWB + ks * 32 + b_col);
                ldsm4(bh[np][0], bh[np][1], bh[np][2], bh[np][3], s0 + OFF_BH + ro);
                if (p3)
                    ldsm4(bl[np][0], bl[np][1], bl[np][2], bl[np][3], s0 + OFF_BH + TILEB + ro);
            }
            // per (mt,nt): hh then hl (same order as gemmP)
#pragma unroll
            for (int mt = 0; mt < 4; ++mt) {
#pragma unroll
                for (int nt = 0; nt < 4; ++nt) {
                    const int np = nt >> 1, sel = (nt & 1) * 2;
                    mma16816(acc[mt][nt], af[mt], &bh[np][sel]);
                    if (p3)
                        mma16816(acc[mt][nt], af[mt], &bl[np][sel]);
                }
            }
            // lazy A-lo pass (3P only), same order as gemmP
            if (p3) {
#pragma unroll
                for (int mt = 0; mt < 4; ++mt) {
                    uint32_t al[4];
                    const uint32_t ro = (uint32_t)((wm + mt * 16 + a_row) * ROWB);
                    ldsm4(al[0], al[1], al[2], al[3], s0 + TILEB + ro + kb);
#pragma unroll
                    for (int nt = 0; nt < 4; ++nt) {
                        const int np = nt >> 1, sel = (nt & 1) * 2;
                        mma16816(acc[mt][nt], al, &bh[np][sel]);
                    }
                }
            }
        }
        __syncthreads();
    }

    // ---- epilogue (fp16 single; alpha=1) ----
    const int gr = lid >> 2;
    const int tg = lid & 3;
#pragma unroll
    for (int mt = 0; mt < 4; ++mt) {
#pragma unroll
        for (int nt = 0; nt < 4; ++nt) {
#pragma unroll
            for (int h = 0; h < 2; ++h) {
                const int m = m0 + wm + mt * 16 + gr + h * 8;
#pragma unroll
                for (int c = 0; c < 2; ++c) {
                    const int n = n0 + wn + nt * 8 + tg * 2 + c;
                    float v = acc[mt][nt][h * 2 + c];
                    v += __ldg(bias + n);
                    f16 hh = __float2half_rn(v);
                    if (z == 0) {
                        g_qp[(long)m * DMOD + n] = hh;
                    } else if (z == 1) {
                        g_kp[(long)m * DMOD + n] = hh;
                    } else {
                        g_vT[(long)(m >> 11) * ((long)DMOD * SEQ) +
                             (long)n * SEQ + (m & 2047)] = hh;
                    }
                }
            }
        }
    }
}

// ----------------------------------------------------------------------------
// 1-product GEMM (NT): C[m,n] = alpha * sum_k A[m,k]*B[n,k] (+bias)
//   mode 0: fp32 out.  mode 1: fp16 single out.
// ----------------------------------------------------------------------------
template <int PROD>
__global__ void __launch_bounds__(256) gemmP(
    const f16* __restrict__ Ahi, const f16* __restrict__ Alo,
    const f16* __restrict__ Bhi, const f16* __restrict__ Blo,
    const float* __restrict__ bias,
    float* __restrict__ Cf, f16* __restrict__ C1, f16* __restrict__ C2,
    int N, int K, int ldc, float alpha,
    long sA, long sB, long sC, int mode, int transC)
{
    constexpr int NT = 2;                // PROD==1 only instantiated
    constexpr int OFF_BH = TILEB;
    constexpr int STAGE  = NT * TILEB;

    extern __shared__ char smem[];
    const uint32_t sb = smem_u32(smem);
    const int tid = threadIdx.x;
    const int wid = tid >> 5;
    const int lid = tid & 31;
    const int wm = (wid & 1) * 64;
    const int wn = (wid >> 1) * 32;
    const long bz = blockIdx.z;
    const int m0 = blockIdx.y * BM;
    const int n0 = blockIdx.x * BN;

    const f16* pAh = Ahi + bz * sA;
    const f16* pBh = Bhi + bz * sB;

    const int lrow = tid >> 2;
    const int lch  = tid & 3;

    float acc[4][4][4];
#pragma unroll
    for (int i = 0; i < 4; ++i)
#pragma unroll
        for (int j = 0; j < 4; ++j)
#pragma unroll
            for (int c = 0; c < 4; ++c) acc[i][j][c] = 0.f;

    const int nch = K / BK;

    auto issue = [&](int ch, int buf) {
        const int k0 = ch * BK;
        const uint32_t s0 = sb + buf * STAGE;
#pragma unroll
        for (int h = 0; h < 2; ++h) {
            const int r = lrow + h * 64;
            const uint32_t so = (uint32_t)(r * ROWB + lch * 16);
            const long goA = (long)(m0 + r) * K + k0 + lch * 8;
            const long goB = (long)(n0 + r) * K + k0 + lch * 8;
            cp16(s0 + so, pAh + goA);
            cp16(s0 + OFF_BH + so, pBh + goB);
        }
    };

    issue(0, 0);
    CP_COMMIT();

    const int a_row = lid & 15;
    const int a_col = (lid >> 4) * 16;
    const int b_nin = ((lid >> 4) & 1) * 8 + (lid & 7);
    const int b_col = ((lid >> 3) & 1) * 16;

    for (int ch = 0; ch < nch; ++ch) {
        if (ch + 1 < nch) { issue(ch + 1, (ch + 1) & 1); CP_COMMIT(); CP_WAIT(1); }
        else              { CP_WAIT(0); }
        __syncthreads();

        const uint32_t s0 = sb + (ch & 1) * STAGE;

#pragma unroll
        for (int ks = 0; ks < 2; ++ks) {
            const int kb = ks * 32 + a_col;
            uint32_t af[4][4];
#pragma unroll
            for (int mt = 0; mt < 4; ++mt) {
                const uint32_t ro = (uint32_t)((wm + mt * 16 + a_row) * ROWB);
                ldsm4(af[mt][0], af[mt][1], af[mt][2], af[mt][3], s0 + ro + kb);
            }
            uint32_t bh[2][4];
#pragma unroll
            for (int np = 0; np < 2; ++np) {
                const uint32_t ro = (uint32_t)((wn + np * 16 + b_nin) * ROWB + ks * 32 + b_col);
                ldsm4(bh[np][0], bh[np][1], bh[np][2], bh[np][3], s0 + OFF_BH + ro);
            }
#pragma unroll
            for (int mt = 0; mt < 4; ++mt)
#pragma unroll
                for (int nt = 0; nt < 4; ++nt)
                    mma16816(acc[mt][nt], af[mt], &bh[nt >> 1][(nt & 1) * 2]);
        }
        __syncthreads();
    }

    const int gr = lid >> 2;
    const int tg = lid & 3;
#pragma unroll
    for (int mt = 0; mt < 4; ++mt) {
#pragma unroll
        for (int nt = 0; nt < 4; ++nt) {
#pragma unroll
            for (int h = 0; h < 2; ++h) {
                const int m = m0 + wm + mt * 16 + gr + h * 8;
#pragma unroll
                for (int c = 0; c < 2; ++c) {
                    const int n = n0 + wn + nt * 8 + tg * 2 + c;
                    float v = acc[mt][nt][h * 2 + c] * alpha;
                    if (bias) v += __ldg(bias + n);
                    if (mode == 0) {
                        Cf[bz * sC + (long)m * ldc + n] = v;
                    } else {
                        long o = transC ? (bz * sC + (long)n * ldc + m)
                                        : (bz * sC + (long)m * ldc + n);
                        C1[o] = __float2half_rn(v);
                    }
                }
            }
        }
    }
}

// ----------------------------------------------------------------------------
// launch
// ----------------------------------------------------------------------------
extern "C" void kernel_launch(void* const* d_in, const int* in_sizes, int n_in,
                              void* d_out, int out_size) {
    const float* q  = (const float*)d_in[0];
    const float* k  = (const float*)d_in[1];
    const float* v  = (const float*)d_in[2];
    const float* Wq = (const float*)d_in[3];
    const float* bq = (const float*)d_in[4];
    const float* Wk = (const float*)d_in[5];
    const float* bk = (const float*)d_in[6];
    const float* Wv = (const float*)d_in[7];
    const float* bv = (const float*)d_in[8];
    const float* Wo = (const float*)d_in[9];
    const float* bo = (const float*)d_in[10];
    float* out = (float*)d_out;

    f16 *qp, *kp, *vT, *at, *av, *wo;
    float* sc;
    cudaGetSymbolAddress((void**)&qp, g_qp);
    cudaGetSymbolAddress((void**)&kp, g_kp);
    cudaGetSymbolAddress((void**)&vT, g_vT);
    cudaGetSymbolAddress((void**)&at, g_at);
    cudaGetSymbolAddress((void**)&av, g_av);
    cudaGetSymbolAddress((void**)&wo, g_wo);
    cudaGetSymbolAddress((void**)&sc, g_sc);

    cudaFuncSetAttribute(proj_qkv, cudaFuncAttributeMaxDynamicSharedMemorySize, SMEM3);
    cudaFuncSetAttribute(gemmP<1>, cudaFuncAttributeMaxDynamicSharedMemorySize, SMEM1);

    const int D = DMOD, S = SEQ, B = BATCH;
    dim3 blk(256);
    dim3 gs(S / BN, S / BM, B);          // (16, 16, 4)
    dim3 ga(D / BN, S / BM, B);          // (8, 16, 4)
    dim3 gp(D / BN, (B * S) / BM, 1);    // (8, 64)

    // 1: all conversions in one launch
    const long NCONV = 3 * NQ + 4 * NW;
    conv_all<<<(unsigned)((NCONV + 511) / 512), 512>>>(q, k, v, Wq, Wk, Wv, Wo);

    // 2: fused q/k/v projections (z = 0,1,2)
    proj_qkv<<<dim3(8, 64, 3), blk, SMEM3>>>(bq, bk, bv);

    // 3: scores (1P: qp x kp) -> fp32
    gemmP<1><<<gs, blk, SMEM1>>>(qp, nullptr, kp, nullptr, nullptr, sc, nullptr, nullptr,
                                 S, D, S, 0.125f,
                                 (long)S * D, (long)S * D, (long)S * S, 0, 0);
    // 4: softmax -> fp16 probs
    softmax_f16<<<(unsigned)(B * S), 256>>>(sc, at, S);
    // 5: av (1P: at x vT) -> fp16 single
    gemmP<1><<<ga, blk, SMEM1>>>(at, nullptr, vT, nullptr, nullptr, nullptr, av, nullptr,
                                 D, S, D, 1.0f,
                                 (long)S * S, (long)D * S, (long)S * D, 1, 0);
    // 6: out (1P: av x wo) + bo -> fp32                 <-- ncu -s 5 -c 1 capture
    gemmP<1><<<gp, blk, SMEM1>>>(av, nullptr, wo, nullptr, bo, out, nullptr, nullptr,
                                 D, D, D, 1.0f, 0, 0, 0, 0, 0);
}

// round 16
// speedup vs baseline: 1.9211x; 1.0555x over previous
#include <cuda_runtime.h>
#include <cuda_fp16.h>
#include <stdint.h>

typedef __half f16;

#define BATCH 4
#define SEQ   2048
#define DMOD  1024

#define NQ ((long)BATCH*SEQ*DMOD)   // 8,388,608
#define NW ((long)DMOD*DMOD)        // 1,048,576
#define NS ((long)BATCH*SEQ*SEQ)    // 16,777,216

// ----------------------------------------------------------------------------
// Scratch (device globals; allocation is forbidden)
// ----------------------------------------------------------------------------
__device__ __align__(256) f16 g_xq_hi[NQ], g_xq_lo[NQ];            // q input, pair
__device__ __align__(256) f16 g_xk_hi[NQ], g_xk_lo[NQ];            // k input, pair
__device__ __align__(256) f16 g_xv[NQ];                            // v input, single
__device__ __align__(256) f16 g_wq_hi[NW], g_wq_lo[NW];
__device__ __align__(256) f16 g_wk_hi[NW], g_wk_lo[NW];
__device__ __align__(256) f16 g_wvT[NW];                           // Wv transposed, single
__device__ __align__(256) f16 g_wo[NW];                            // Wo, single
__device__ __align__(256) f16 g_wc[NW];                            // Wc = Wo@Wv, single
__device__ __align__(256) float g_bc[DMOD];                        // bc = bv@Wo^T + bo
__device__ __align__(256) f16 g_qp[NQ];                            // q-proj, single
__device__ __align__(256) f16 g_kp[NQ];                            // k-proj, single
__device__ __align__(256) f16 g_uT[NQ];                            // u = xv@Wc^T, [B][D][S]
__device__ __align__(256) float g_sc[NS];                          // scores fp32
__device__ __align__(256) f16 g_at[NS];                            // probs, single

// ----------------------------------------------------------------------------
// helpers
// ----------------------------------------------------------------------------
__device__ __forceinline__ uint32_t smem_u32(const void* p) {
    uint32_t a;
    asm("{ .reg .u64 t; cvta.to.shared.u64 t, %1; cvt.u32.u64 %0, t; }" : "=r"(a) : "l"(p));
    return a;
}
__device__ __forceinline__ void cp16(uint32_t s, const void* g) {
    asm volatile("cp.async.cg.shared.global [%0], [%1], 16;" :: "r"(s), "l"(g));
}
#define CP_COMMIT() asm volatile("cp.async.commit_group;" ::: "memory")
#define CP_WAIT(n)  asm volatile("cp.async.wait_group %0;" :: "n"(n) : "memory")

__device__ __forceinline__ void ldsm4(uint32_t& r0, uint32_t& r1, uint32_t& r2,
                                      uint32_t& r3, uint32_t addr) {
    asm volatile("ldmatrix.sync.aligned.m8n8.x4.shared.b16 {%0,%1,%2,%3}, [%4];"
                 : "=r"(r0), "=r"(r1), "=r"(r2), "=r"(r3) : "r"(addr));
}
__device__ __forceinline__ void mma16816(float* d, const uint32_t* a, const uint32_t* b) {
    asm volatile(
        "mma.sync.aligned.m16n8k16.row.col.f32.f16.f16.f32 "
        "{%0,%1,%2,%3}, {%4,%5,%6,%7}, {%8,%9}, {%0,%1,%2,%3};"
        : "+f"(d[0]), "+f"(d[1]), "+f"(d[2]), "+f"(d[3])
        : "r"(a[0]), "r"(a[1]), "r"(a[2]), "r"(a[3]), "r"(b[0]), "r"(b[1]));
}

// ----------------------------------------------------------------------------
// fused conversions: xq/xk pairs, xv single, wq/wk pairs, wo single
// ----------------------------------------------------------------------------
__global__ void conv_all(const float* __restrict__ q, const float* __restrict__ k,
                         const float* __restrict__ v,
                         const float* __restrict__ wq, const float* __restrict__ wk,
                         const float* __restrict__ wo) {
    long i = (long)blockIdx.x * blockDim.x + threadIdx.x;
    if (i < 3 * NQ) {
        if (i < NQ) {
            float val = q[i];
            f16 h = __float2half_rn(val);
            g_xq_hi[i] = h;
            g_xq_lo[i] = __float2half_rn(val - __half2float(h));
        } else if (i < 2 * NQ) {
            long j = i - NQ;
            float val = k[j];
            f16 h = __float2half_rn(val);
            g_xk_hi[j] = h;
            g_xk_lo[j] = __float2half_rn(val - __half2float(h));
        } else {
            long j = i - 2 * NQ;
            g_xv[j] = __float2half_rn(v[j]);
        }
        return;
    }
    long w = i - 3 * NQ;
    if (w >= 3 * NW) return;
    if (w < 2 * NW) {
        const float* src; f16 *hi, *lo; long j;
        if (w < NW) { src = wq; hi = g_wq_hi; lo = g_wq_lo; j = w; }
        else        { src = wk; hi = g_wk_hi; lo = g_wk_lo; j = w - NW; }
        float val = src[j];
        f16 h = __float2half_rn(val);
        hi[j] = h;
        lo[j] = __float2half_rn(val - __half2float(h));
    } else {
        long j = w - 2 * NW;
        g_wo[j] = __float2half_rn(wo[j]);
    }
}

// ----------------------------------------------------------------------------
// Wv (fp32 [D][D]) -> g_wvT (fp16 [D][D], transposed), coalesced tiled transpose
// ----------------------------------------------------------------------------
__global__ void transp_wv(const float* __restrict__ wv) {
    __shared__ float t[32][33];
    const int bx = blockIdx.x * 32, by = blockIdx.y * 32;
    const int tx = threadIdx.x, ty = threadIdx.y;       // (32, 8)
#pragma unroll
    for (int i = 0; i < 4; ++i)
        t[ty + i * 8][tx] = wv[(long)(by + ty + i * 8) * DMOD + bx + tx];
    __syncthreads();
#pragma unroll
    for (int i = 0; i < 4; ++i)
        g_wvT[(long)(bx + ty + i * 8) * DMOD + by + tx] =
            __float2half_rn(t[tx][ty + i * 8]);
}

// ----------------------------------------------------------------------------
// bc[n] = bo[n] + sum_j bv[j] * Wo[n][j]   (exact fp32; one block per n)
// ----------------------------------------------------------------------------
__global__ void bias_comb(const float* __restrict__ bv, const float* __restrict__ wo,
                          const float* __restrict__ bo) {
    __shared__ float red[256];
    const int n = blockIdx.x, t = threadIdx.x;
    float s = 0.f;
    for (int j = t; j < DMOD; j += 256) s += bv[j] * wo[(long)n * DMOD + j];
    red[t] = s; __syncthreads();
    for (int k = 128; k > 0; k >>= 1) {
        if (t < k) red[t] += red[t + k];
        __syncthreads();
    }
    if (t == 0) g_bc[n] = bo[n] + red[0];
}

// ----------------------------------------------------------------------------
// Row softmax fp32 -> fp16   (n == 2048, 256 threads)
// ----------------------------------------------------------------------------
__global__ void softmax_f16(const float* __restrict__ S, f16* __restrict__ P, int n) {
    const float* row = S + (long)blockIdx.x * n;
    __shared__ float red[256];
    const int t = threadIdx.x;
    float e[8];
    float m = -1e30f;
#pragma unroll
    for (int i = 0; i < 8; i++) { e[i] = row[t + i * 256]; m = fmaxf(m, e[i]); }
    red[t] = m; __syncthreads();
    for (int s = 128; s > 0; s >>= 1) {
        if (t < s) red[t] = fmaxf(red[t], red[t + s]);
        __syncthreads();
    }
    m = red[0]; __syncthreads();
    float sum = 0.f;
#pragma unroll
    for (int i = 0; i < 8; i++) { e[i] = __expf(e[i] - m); sum += e[i]; }
    red[t] = sum; __syncthreads();
    for (int s = 128; s > 0; s >>= 1) {
        if (t < s) red[t] += red[t + s];
        __syncthreads();
    }
    float inv = 1.0f / red[0];
#pragma unroll
    for (int i = 0; i < 8; i++)
        P[(long)blockIdx.x * n + t + i * 256] = __float2half_rn(e[i] * inv);
}

// ----------------------------------------------------------------------------
// GEMM geometry
// ----------------------------------------------------------------------------
#define BM 128
#define BN 128
#define BK 32
#define ROWB 80
#define TILEB (128 * ROWB)      // 10240
#define SMEM1 (2 * 2 * TILEB)   // 40960
#define SMEM3 (2 * 4 * TILEB)   // 81920

// ----------------------------------------------------------------------------
// Fused QKV/U projection: grid (8, 64, 3); z=0 q (3P), z=1 k (3P), z=2 u (1P).
// z=2: u = xv @ Wc^T, no bias, transposed output [B][D][S].
// ----------------------------------------------------------------------------
__global__ void __launch_bounds__(256) proj_qkv(
    const float* __restrict__ bq, const float* __restrict__ bk)
{
    extern __shared__ char smem[];
    const uint32_t sb = smem_u32(smem);
    const int tid = threadIdx.x;
    const int wid = tid >> 5;
    const int lid = tid & 31;
    const int wm = (wid & 1) * 64;
    const int wn = (wid >> 1) * 32;
    const int z  = blockIdx.z;
    const bool p3 = (z < 2);
    const int m0 = blockIdx.y * BM;
    const int n0 = blockIdx.x * BN;
    const int K = DMOD;

    const f16 *pAh, *pAl, *pBh, *pBl;
    const float* bias;
    if (z == 0)      { pAh = g_xq_hi; pAl = g_xq_lo; pBh = g_wq_hi; pBl = g_wq_lo; bias = bq; }
    else if (z == 1) { pAh = g_xk_hi; pAl = g_xk_lo; pBh = g_wk_hi; pBl = g_wk_lo; bias = bk; }
    else             { pAh = g_xv;    pAl = nullptr;  pBh = g_wc;    pBl = nullptr;  bias = nullptr; }

    const uint32_t OFF_BH = p3 ? 2 * TILEB : TILEB;
    const uint32_t STAGE  = p3 ? 4 * TILEB : 2 * TILEB;

    const int lrow = tid >> 2;
    const int lch  = tid & 3;

    float acc[4][4][4];
#pragma unroll
    for (int i = 0; i < 4; ++i)
#pragma unroll
        for (int j = 0; j < 4; ++j)
#pragma unroll
            for (int c = 0; c < 4; ++c) acc[i][j][c] = 0.f;

    const int nch = K / BK;

    auto issue = [&](int ch, int buf) {
        const int k0 = ch * BK;
        const uint32_t s0 = sb + buf * STAGE;
#pragma unroll
        for (int h = 0; h < 2; ++h) {
            const int r = lrow + h * 64;
            const uint32_t so = (uint32_t)(r * ROWB + lch * 16);
            const long goA = (long)(m0 + r) * K + k0 + lch * 8;
            const long goB = (long)(n0 + r) * K + k0 + lch * 8;
            cp16(s0 + so, pAh + goA);
            if (p3) cp16(s0 + TILEB + so, pAl + goA);
            cp16(s0 + OFF_BH + so, pBh + goB);
            if (p3) cp16(s0 + OFF_BH + TILEB + so, pBl + goB);
        }
    };

    issue(0, 0);
    CP_COMMIT();

    const int a_row = lid & 15;
    const int a_col = (lid >> 4) * 16;
    const int b_nin = ((lid >> 4) & 1) * 8 + (lid & 7);
    const int b_col = ((lid >> 3) & 1) * 16;

    for (int ch = 0; ch < nch; ++ch) {
        if (ch + 1 < nch) { issue(ch + 1, (ch + 1) & 1); CP_COMMIT(); CP_WAIT(1); }
        else              { CP_WAIT(0); }
        __syncthreads();

        const uint32_t s0 = sb + (ch & 1) * STAGE;

#pragma unroll
        for (int ks = 0; ks < 2; ++ks) {
            const int kb = ks * 32 + a_col;
            uint32_t af[4][4];
#pragma unroll
            for (int mt = 0; mt < 4; ++mt) {
                const uint32_t ro = (uint32_t)((wm + mt * 16 + a_row) * ROWB);
                ldsm4(af[mt][0], af[mt][1], af[mt][2], af[mt][3], s0 + ro + kb);
            }
            uint32_t bh[2][4], bl[2][4];
#pragma unroll
            for (int np = 0; np < 2; ++np) {
                const uint32_t ro = (uint32_t)((wn + np * 16 + b_nin) * ROWB + ks * 32 + b_col);
                ldsm4(bh[np][0], bh[np][1], bh[np][2], bh[np][3], s0 + OFF_BH + ro);
                if (p3)
                    ldsm4(bl[np][0], bl[np][1], bl[np][2], bl[np][3], s0 + OFF_BH + TILEB + ro);
            }
#pragma unroll
            for (int mt = 0; mt < 4; ++mt) {
#pragma unroll
                for (int nt = 0; nt < 4; ++nt) {
                    const int np = nt >> 1, sel = (nt & 1) * 2;
                    mma16816(acc[mt][nt], af[mt], &bh[np][sel]);
                    if (p3)
                        mma16816(acc[mt][nt], af[mt], &bl[np][sel]);
                }
            }
            if (p3) {
#pragma unroll
                for (int mt = 0; mt < 4; ++mt) {
                    uint32_t al[4];
                    const uint32_t ro = (uint32_t)((wm + mt * 16 + a_row) * ROWB);
                    ldsm4(al[0], al[1], al[2], al[3], s0 + TILEB + ro + kb);
#pragma unroll
                    for (int nt = 0; nt < 4; ++nt) {
                        const int np = nt >> 1, sel = (nt & 1) * 2;
                        mma16816(acc[mt][nt], al, &bh[np][sel]);
                    }
                }
            }
        }
        __syncthreads();
    }

    // ---- epilogue ----
    const int gr = lid >> 2;
    const int tg = lid & 3;
#pragma unroll
    for (int mt = 0; mt < 4; ++mt) {
#pragma unroll
        for (int nt = 0; nt < 4; ++nt) {
#pragma unroll
            for (int h = 0; h < 2; ++h) {
                const int m = m0 + wm + mt * 16 + gr + h * 8;
#pragma unroll
                for (int c = 0; c < 2; ++c) {
                    const int n = n0 + wn + nt * 8 + tg * 2 + c;
                    float v = acc[mt][nt][h * 2 + c];
                    if (bias) v += __ldg(bias + n);
                    f16 hh = __float2half_rn(v);
                    if (z == 0) {
                        g_qp[(long)m * DMOD + n] = hh;
                    } else if (z == 1) {
                        g_kp[(long)m * DMOD + n] = hh;
                    } else {
                        g_uT[(long)(m >> 11) * ((long)DMOD * SEQ) +
                             (long)n * SEQ + (m & 2047)] = hh;
                    }
                }
            }
        }
    }
}

// ----------------------------------------------------------------------------
// 1-product GEMM (NT): C[m,n] = alpha * sum_k A[m,k]*B[n,k] (+bias)
//   mode 0: fp32 out.  mode 1: fp16 single out.
// ----------------------------------------------------------------------------
__global__ void __launch_bounds__(256) gemm1(
    const f16* __restrict__ A, const f16* __restrict__ B,
    const float* __restrict__ bias,
    float* __restrict__ Cf, f16* __restrict__ C1,
    int N, int K, int ldc, float alpha,
    long sA, long sB, long sC, int mode)
{
    constexpr int OFF_BH = TILEB;
    constexpr int STAGE  = 2 * TILEB;

    extern __shared__ char smem[];
    const uint32_t sb = smem_u32(smem);
    const int tid = threadIdx.x;
    const int wid = tid >> 5;
    const int lid = tid & 31;
    const int wm = (wid & 1) * 64;
    const int wn = (wid >> 1) * 32;
    const long bz = blockIdx.z;
    const int m0 = blockIdx.y * BM;
    const int n0 = blockIdx.x * BN;

    const f16* pAh = A + bz * sA;
    const f16* pBh = B + bz * sB;

    const int lrow = tid >> 2;
    const int lch  = tid & 3;

    float acc[4][4][4];
#pragma unroll
    for (int i = 0; i < 4; ++i)
#pragma unroll
        for (int j = 0; j < 4; ++j)
#pragma unroll
            for (int c = 0; c < 4; ++c) acc[i][j][c] = 0.f;

    const int nch = K / BK;

    auto issue = [&](int ch, int buf) {
        const int k0 = ch * BK;
        const uint32_t s0 = sb + buf * STAGE;
#pragma unroll
        for (int h = 0; h < 2; ++h) {
            const int r = lrow + h * 64;
            const uint32_t so = (uint32_t)(r * ROWB + lch * 16);
            const long goA = (long)(m0 + r) * K + k0 + lch * 8;
            const long goB = (long)(n0 + r) * K + k0 + lch * 8;
            cp16(s0 + so, pAh + goA);
            cp16(s0 + OFF_BH + so, pBh + goB);
        }
    };

    issue(0, 0);
    CP_COMMIT();

    const int a_row = lid & 15;
    const int a_col = (lid >> 4) * 16;
    const int b_nin = ((lid >> 4) & 1) * 8 + (lid & 7);
    const int b_col = ((lid >> 3) & 1) * 16;

    for (int ch = 0; ch < nch; ++ch) {
        if (ch + 1 < nch) { issue(ch + 1, (ch + 1) & 1); CP_COMMIT(); CP_WAIT(1); }
        else              { CP_WAIT(0); }
        __syncthreads();

        const uint32_t s0 = sb + (ch & 1) * STAGE;

#pragma unroll
        for (int ks = 0; ks < 2; ++ks) {
            const int kb = ks * 32 + a_col;
            uint32_t af[4][4];
#pragma unroll
            for (int mt = 0; mt < 4; ++mt) {
                const uint32_t ro = (uint32_t)((wm + mt * 16 + a_row) * ROWB);
                ldsm4(af[mt][0], af[mt][1], af[mt][2], af[mt][3], s0 + ro + kb);
            }
            uint32_t bh[2][4];
#pragma unroll
            for (int np = 0; np < 2; ++np) {
                const uint32_t ro = (uint32_t)((wn + np * 16 + b_nin) * ROWB + ks * 32 + b_col);
                ldsm4(bh[np][0], bh[np][1], bh[np][2], bh[np][3], s0 + OFF_BH + ro);
            }
#pragma unroll
            for (int mt = 0; mt < 4; ++mt)
#pragma unroll
                for (int nt = 0; nt < 4; ++nt)
                    mma16816(acc[mt][nt], af[mt], &bh[nt >> 1][(nt & 1) * 2]);
        }
        __syncthreads();
    }

    const int gr = lid >> 2;
    const int tg = lid & 3;
#pragma unroll
    for (int mt = 0; mt < 4; ++mt) {
#pragma unroll
        for (int nt = 0; nt < 4; ++nt) {
#pragma unroll
            for (int h = 0; h < 2; ++h) {
                const int m = m0 + wm + mt * 16 + gr + h * 8;
#pragma unroll
                for (int c = 0; c < 2; ++c) {
                    const int n = n0 + wn + nt * 8 + tg * 2 + c;
                    float v = acc[mt][nt][h * 2 + c] * alpha;
                    if (bias) v += __ldg(bias + n);
                    if (mode == 0) {
                        Cf[bz * sC + (long)m * ldc + n] = v;
                    } else {
                        C1[bz * sC + (long)m * ldc + n] = __float2half_rn(v);
                    }
                }
            }
        }
    }
}

// ----------------------------------------------------------------------------
// launch
// ----------------------------------------------------------------------------
extern "C" void kernel_launch(void* const* d_in, const int* in_sizes, int n_in,
                              void* d_out, int out_size) {
    const float* q  = (const float*)d_in[0];
    const float* k  = (const float*)d_in[1];
    const float* v  = (const float*)d_in[2];
    const float* Wq = (const float*)d_in[3];
    const float* bq = (const float*)d_in[4];
    const float* Wk = (const float*)d_in[5];
    const float* bk = (const float*)d_in[6];
    const float* Wv = (const float*)d_in[7];
    const float* bv = (const float*)d_in[8];
    const float* Wo = (const float*)d_in[9];
    const float* bo = (const float*)d_in[10];
    float* out = (float*)d_out;

    f16 *qp, *kp, *uT, *at, *wo, *wvT, *wc;
    float *sc, *bc;
    cudaGetSymbolAddress((void**)&qp,  g_qp);
    cudaGetSymbolAddress((void**)&kp,  g_kp);
    cudaGetSymbolAddress((void**)&uT,  g_uT);
    cudaGetSymbolAddress((void**)&at,  g_at);
    cudaGetSymbolAddress((void**)&wo,  g_wo);
    cudaGetSymbolAddress((void**)&wvT, g_wvT);
    cudaGetSymbolAddress((void**)&wc,  g_wc);
    cudaGetSymbolAddress((void**)&sc,  g_sc);
    cudaGetSymbolAddress((void**)&bc,  g_bc);

    cudaFuncSetAttribute(proj_qkv, cudaFuncAttributeMaxDynamicSharedMemorySize, SMEM3);
    cudaFuncSetAttribute(gemm1,    cudaFuncAttributeMaxDynamicSharedMemorySize, SMEM1);

    const int D = DMOD, S = SEQ, B = BATCH;
    dim3 blk(256);
    dim3 gs(S / BN, S / BM, B);          // (16, 16, 4)
    dim3 go(D / BN, S / BM, B);          // (8, 16, 4)

    // 1: conversions (xq/xk pairs, xv, wq/wk pairs, wo)
    const long NCONV = 3 * NQ + 3 * NW;
    conv_all<<<(unsigned)((NCONV + 511) / 512), 512>>>(q, k, v, Wq, Wk, Wo);
    // 2: WvT (fp16, transposed)
    transp_wv<<<dim3(32, 32), dim3(32, 8)>>>(Wv);
    // 3: bc = bv @ Wo^T + bo (exact fp32)
    bias_comb<<<DMOD, 256>>>(bv, Wo, bo);
    // 4: Wc = Wo @ Wv (fp16 1P GEMM)
    gemm1<<<dim3(8, 8), blk, SMEM1>>>(wo, wvT, nullptr, nullptr, wc,
                                      D, D, D, 1.0f, 0, 0, 0, 1);
    // 5: fused q/k/u projections
    proj_qkv<<<dim3(8, 64, 3), blk, SMEM3>>>(bq, bk);
    // 6: scores (1P: qp x kp) -> fp32                   <-- ncu -s 5 -c 1 capture
    gemm1<<<gs, blk, SMEM1>>>(qp, kp, nullptr, sc, nullptr,
                              S, D, S, 0.125f,
                              (long)S * D, (long)S * D, (long)S * S, 0);
    // 7: softmax -> fp16 probs
    softmax_f16<<<(unsigned)(B * S), 256>>>(sc, at, S);
    // 8: out = P @ u + bc -> fp32 (direct to d_out)
    gemm1<<<go, blk, SMEM1>>>(at, uT, bc, out, nullptr,
                              D, S, D, 1.0f,
                              (long)S * S, (long)D * S, (long)S * D, 0);
}

// round 17
// speedup vs baseline: 1.9935x; 1.0377x over previous
#include <cuda_runtime.h>
#include <cuda_fp16.h>
#include <stdint.h>

typedef __half f16;

#define BATCH 4
#define SEQ   2048
#define DMOD  1024

#define NQ ((long)BATCH*SEQ*DMOD)   // 8,388,608
#define NW ((long)DMOD*DMOD)        // 1,048,576
#define NS ((long)BATCH*SEQ*SEQ)    // 16,777,216
#define NBS ((long)BATCH*SEQ)       // 8192

// ----------------------------------------------------------------------------
// Scratch (device globals; allocation is forbidden)
// ----------------------------------------------------------------------------
__device__ __align__(256) f16 g_xq_hi[NQ], g_xq_lo[NQ];            // q input, pair
__device__ __align__(256) f16 g_xk_hi[NQ], g_xk_lo[NQ];            // k input, pair
__device__ __align__(256) f16 g_xv[NQ];                            // v input, single
__device__ __align__(256) f16 g_wqT_hi[NW], g_wqT_lo[NW];          // Wq^T, pair
__device__ __align__(256) f16 g_wkT_hi[NW], g_wkT_lo[NW];          // Wk^T, pair
__device__ __align__(256) f16 g_wvT[NW];                           // Wv^T, single
__device__ __align__(256) f16 g_wo[NW];                            // Wo, single
__device__ __align__(256) f16 g_m_hi[NW], g_m_lo[NW];              // M = Wq^T Wk, pair
__device__ __align__(256) f16 g_wc[NW];                            // Wc = Wo@Wv, single
__device__ __align__(256) float g_bc[DMOD];                        // bc = bv@Wo^T + bo
__device__ __align__(256) float g_w1[DMOD];                        // w1 = Wk^T bq
__device__ __align__(256) float g_rk[NBS];                         // 0.125 * xk@w1
__device__ __align__(256) f16 g_zk[NQ];                            // zk = xk@M^T, single
__device__ __align__(256) f16 g_uT[NQ];                            // u = xv@Wc^T, [B][D][S]
__device__ __align__(256) float g_sc[NS];                          // raw scores fp32
__device__ __align__(256) f16 g_at[NS];                            // probs, single

// ----------------------------------------------------------------------------
// helpers
// ----------------------------------------------------------------------------
__device__ __forceinline__ uint32_t smem_u32(const void* p) {
    uint32_t a;
    asm("{ .reg .u64 t; cvta.to.shared.u64 t, %1; cvt.u32.u64 %0, t; }" : "=r"(a) : "l"(p));
    return a;
}
__device__ __forceinline__ void cp16(uint32_t s, const void* g) {
    asm volatile("cp.async.cg.shared.global [%0], [%1], 16;" :: "r"(s), "l"(g));
}
#define CP_COMMIT() asm volatile("cp.async.commit_group;" ::: "memory")
#define CP_WAIT(n)  asm volatile("cp.async.wait_group %0;" :: "n"(n) : "memory")

__device__ __forceinline__ void ldsm4(uint32_t& r0, uint32_t& r1, uint32_t& r2,
                                      uint32_t& r3, uint32_t addr) {
    asm volatile("ldmatrix.sync.aligned.m8n8.x4.shared.b16 {%0,%1,%2,%3}, [%4];"
                 : "=r"(r0), "=r"(r1), "=r"(r2), "=r"(r3) : "r"(addr));
}
__device__ __forceinline__ void mma16816(float* d, const uint32_t* a, const uint32_t* b) {
    asm volatile(
        "mma.sync.aligned.m16n8k16.row.col.f32.f16.f16.f32 "
        "{%0,%1,%2,%3}, {%4,%5,%6,%7}, {%8,%9}, {%0,%1,%2,%3};"
        : "+f"(d[0]), "+f"(d[1]), "+f"(d[2]), "+f"(d[3])
        : "r"(a[0]), "r"(a[1]), "r"(a[2]), "r"(a[3]), "r"(b[0]), "r"(b[1]));
}

// ----------------------------------------------------------------------------
// conversions: xq/xk pairs, xv single, wo single
// ----------------------------------------------------------------------------
__global__ void conv_all(const float* __restrict__ q, const float* __restrict__ k,
                         const float* __restrict__ v, const float* __restrict__ wo) {
    long i = (long)blockIdx.x * blockDim.x + threadIdx.x;
    if (i < 3 * NQ) {
        if (i < NQ) {
            float val = q[i];
            f16 h = __float2half_rn(val);
            g_xq_hi[i] = h;
            g_xq_lo[i] = __float2half_rn(val - __half2float(h));
        } else if (i < 2 * NQ) {
            long j = i - NQ;
            float val = k[j];
            f16 h = __float2half_rn(val);
            g_xk_hi[j] = h;
            g_xk_lo[j] = __float2half_rn(val - __half2float(h));
        } else {
            long j = i - 2 * NQ;
            g_xv[j] = __float2half_rn(v[j]);
        }
        return;
    }
    long w = i - 3 * NQ;
    if (w < NW) g_wo[w] = __float2half_rn(wo[w]);
}

// ----------------------------------------------------------------------------
// fused transposes: z=0 WqT pair, z=1 WkT pair, z=2 WvT single
// ----------------------------------------------------------------------------
__global__ void transp3(const float* __restrict__ wq, const float* __restrict__ wk,
                        const float* __restrict__ wv) {
    __shared__ float t[32][33];
    const int z = blockIdx.z;
    const float* src = (z == 0) ? wq : (z == 1) ? wk : wv;
    const int bx = blockIdx.x * 32, by = blockIdx.y * 32;
    const int tx = threadIdx.x, ty = threadIdx.y;       // (32, 8)
#pragma unroll
    for (int i = 0; i < 4; ++i)
        t[ty + i * 8][tx] = src[(long)(by + ty + i * 8) * DMOD + bx + tx];
    __syncthreads();
#pragma unroll
    for (int i = 0; i < 4; ++i) {
        float val = t[tx][ty + i * 8];
        long o = (long)(bx + ty + i * 8) * DMOD + by + tx;
        f16 h = __float2half_rn(val);
        if (z == 0) {
            g_wqT_hi[o] = h;
            g_wqT_lo[o] = __float2half_rn(val - __half2float(h));
        } else if (z == 1) {
            g_wkT_hi[o] = h;
            g_wkT_lo[o] = __float2half_rn(val - __half2float(h));
        } else {
            g_wvT[o] = h;
        }
    }
}

// ----------------------------------------------------------------------------
// small bias combos: blocks [0,1024): bc[n] = bo[n] + bv@Wo[n,:];
//                    blocks [1024,1028): w1[e] = sum_a bq[a]*Wk[a,e]
// ----------------------------------------------------------------------------
__global__ void small_bias(const float* __restrict__ bv, const float* __restrict__ wo,
                           const float* __restrict__ bo, const float* __restrict__ bq,
                           const float* __restrict__ wk) {
    if (blockIdx.x < 1024) {
        __shared__ float red[256];
        const int n = blockIdx.x, t = threadIdx.x;
        float s = 0.f;
        for (int j = t; j < DMOD; j += 256) s += bv[j] * wo[(long)n * DMOD + j];
        red[t] = s; __syncthreads();
        for (int k = 128; k > 0; k >>= 1) {
            if (t < k) red[t] += red[t + k];
            __syncthreads();
        }
        if (t == 0) g_bc[n] = bo[n] + red[0];
    } else {
        const int e = (blockIdx.x - 1024) * 256 + threadIdx.x;
        float s = 0.f;
        for (int a = 0; a < DMOD; ++a) s += bq[a] * wk[(long)a * DMOD + e];
        g_w1[e] = s;
    }
}

// ----------------------------------------------------------------------------
// rk[j] = 0.125 * xk[j] . w1   (fp32; one block per row)
// ----------------------------------------------------------------------------
__global__ void rk_gemv(const float* __restrict__ k) {
    __shared__ float red[256];
    const long j = blockIdx.x;
    const int t = threadIdx.x;
    const float* row = k + j * DMOD;
    float s = 0.f;
    for (int e = t; e < DMOD; e += 256) s += row[e] * g_w1[e];
    red[t] = s; __syncthreads();
    for (int b = 128; b > 0; b >>= 1) {
        if (t < b) red[t] += red[t + b];
        __syncthreads();
    }
    if (t == 0) g_rk[j] = 0.125f * red[0];
}

// ----------------------------------------------------------------------------
// Row softmax with column correction: e = exp(row[j] + rk[j] - max)
// ----------------------------------------------------------------------------
__global__ void softmax_f16(const float* __restrict__ S, f16* __restrict__ P, int n) {
    const float* row = S + (long)blockIdx.x * n;
    const float* rkp = g_rk + (long)(blockIdx.x >> 11) * SEQ;
    __shared__ float red[256];
    const int t = threadIdx.x;
    float e[8];
    float m = -1e30f;
#pragma unroll
    for (int i = 0; i < 8; i++) {
        e[i] = row[t + i * 256] + rkp[t + i * 256];
        m = fmaxf(m, e[i]);
    }
    red[t] = m; __syncthreads();
    for (int s = 128; s > 0; s >>= 1) {
        if (t < s) red[t] = fmaxf(red[t], red[t + s]);
        __syncthreads();
    }
    m = red[0]; __syncthreads();
    float sum = 0.f;
#pragma unroll
    for (int i = 0; i < 8; i++) { e[i] = __expf(e[i] - m); sum += e[i]; }
    red[t] = sum; __syncthreads();
    for (int s = 128; s > 0; s >>= 1) {
        if (t < s) red[t] += red[t + s];
        __syncthreads();
    }
    float inv = 1.0f / red[0];
#pragma unroll
    for (int i = 0; i < 8; i++)
        P[(long)blockIdx.x * n + t + i * 256] = __float2half_rn(e[i] * inv);
}

// ----------------------------------------------------------------------------
// GEMM geometry
// ----------------------------------------------------------------------------
#define BM 128
#define BN 128
#define BK 32
#define ROWB 80
#define TILEB (128 * ROWB)      // 10240
#define SMEM1 (2 * 2 * TILEB)   // 40960
#define SMEM3 (2 * 4 * TILEB)   // 81920

// ----------------------------------------------------------------------------
// Shared GEMM body: NT, CTA 128x128, BK=32, 2-stage cp.async, 8 warps.
// p3: (Ah+Al)x(Bh+Bl) minus lolo.  !p3: Ah x Bh.
// ----------------------------------------------------------------------------
__device__ __forceinline__ void gemm_body(
    const f16* pAh, const f16* pAl, const f16* pBh, const f16* pBl,
    bool p3, int K, int m0, int n0, char* smem, float (&acc)[4][4][4])
{
    const uint32_t sb = smem_u32(smem);
    const int tid = threadIdx.x;
    const int wid = tid >> 5;
    const int lid = tid & 31;
    const int wm = (wid & 1) * 64;
    const int wn = (wid >> 1) * 32;

    const uint32_t OFF_BH = p3 ? 2 * TILEB : TILEB;
    const uint32_t STAGE  = p3 ? 4 * TILEB : 2 * TILEB;

    const int lrow = tid >> 2;
    const int lch  = tid & 3;

#pragma unroll
    for (int i = 0; i < 4; ++i)
#pragma unroll
        for (int j = 0; j < 4; ++j)
#pragma unroll
            for (int c = 0; c < 4; ++c) acc[i][j][c] = 0.f;

    const int nch = K / BK;

    auto issue = [&](int ch, int buf) {
        const int k0 = ch * BK;
        const uint32_t s0 = sb + buf * STAGE;
#pragma unroll
        for (int h = 0; h < 2; ++h) {
            const int r = lrow + h * 64;
            const uint32_t so = (uint32_t)(r * ROWB + lch * 16);
            const long goA = (long)(m0 + r) * K + k0 + lch * 8;
            const long goB = (long)(n0 + r) * K + k0 + lch * 8;
            cp16(s0 + so, pAh + goA);
            if (p3) cp16(s0 + TILEB + so, pAl + goA);
            cp16(s0 + OFF_BH + so, pBh + goB);
            if (p3) cp16(s0 + OFF_BH + TILEB + so, pBl + goB);
        }
    };

    issue(0, 0);
    CP_COMMIT();

    const int a_row = lid & 15;
    const int a_col = (lid >> 4) * 16;
    const int b_nin = ((lid >> 4) & 1) * 8 + (lid & 7);
    const int b_col = ((lid >> 3) & 1) * 16;

    for (int ch = 0; ch < nch; ++ch) {
        if (ch + 1 < nch) { issue(ch + 1, (ch + 1) & 1); CP_COMMIT(); CP_WAIT(1); }
        else              { CP_WAIT(0); }
        __syncthreads();

        const uint32_t s0 = sb + (ch & 1) * STAGE;

#pragma unroll
        for (int ks = 0; ks < 2; ++ks) {
            const int kb = ks * 32 + a_col;
            uint32_t af[4][4];
#pragma unroll
            for (int mt = 0; mt < 4; ++mt) {
                const uint32_t ro = (uint32_t)((wm + mt * 16 + a_row) * ROWB);
                ldsm4(af[mt][0], af[mt][1], af[mt][2], af[mt][3], s0 + ro + kb);
            }
            uint32_t bh[2][4], bl[2][4];
#pragma unroll
            for (int np = 0; np < 2; ++np) {
                const uint32_t ro = (uint32_t)((wn + np * 16 + b_nin) * ROWB + ks * 32 + b_col);
                ldsm4(bh[np][0], bh[np][1], bh[np][2], bh[np][3], s0 + OFF_BH + ro);
                if (p3)
                    ldsm4(bl[np][0], bl[np][1], bl[np][2], bl[np][3], s0 + OFF_BH + TILEB + ro);
            }
#pragma unroll
            for (int mt = 0; mt < 4; ++mt) {
#pragma unroll
                for (int nt = 0; nt < 4; ++nt) {
                    const int np = nt >> 1, sel = (nt & 1) * 2;
                    mma16816(acc[mt][nt], af[mt], &bh[np][sel]);
                    if (p3)
                        mma16816(acc[mt][nt], af[mt], &bl[np][sel]);
                }
            }
            if (p3) {
#pragma unroll
                for (int mt = 0; mt < 4; ++mt) {
                    uint32_t al[4];
                    const uint32_t ro = (uint32_t)((wm + mt * 16 + a_row) * ROWB);
                    ldsm4(al[0], al[1], al[2], al[3], s0 + TILEB + ro + kb);
#pragma unroll
                    for (int nt = 0; nt < 4; ++nt) {
                        const int np = nt >> 1, sel = (nt & 1) * 2;
                        mma16816(acc[mt][nt], al, &bh[np][sel]);
                    }
                }
            }
        }
        __syncthreads();
    }
}

// epilogue index macro
#define EPI_LOOP(body)                                                        \
    {                                                                         \
        const int wid_ = threadIdx.x >> 5, lid_ = threadIdx.x & 31;           \
        const int wm_ = (wid_ & 1) * 64, wn_ = (wid_ >> 1) * 32;              \
        const int gr = lid_ >> 2, tg = lid_ & 3;                              \
        _Pragma("unroll")                                                     \
        for (int mt = 0; mt < 4; ++mt)                                        \
        _Pragma("unroll")                                                     \
        for (int nt = 0; nt < 4; ++nt)                                        \
        _Pragma("unroll")                                                     \
        for (int h = 0; h < 2; ++h)                                           \
        _Pragma("unroll")                                                     \
        for (int c = 0; c < 2; ++c) {                                         \
            const int mloc = wm_ + mt * 16 + gr + h * 8;                      \
            const int nloc = wn_ + nt * 8 + tg * 2 + c;                       \
            float v = acc[mt][nt][h * 2 + c];                                 \
            body                                                              \
        }                                                                     \
    }

// ----------------------------------------------------------------------------
// fused weight GEMMs: grid (8,8,2). z=0: M = WqT x WkT (3P, pair out);
//                                   z=1: Wc = Wo x WvT (1P, single out).
// ----------------------------------------------------------------------------
__global__ void __launch_bounds__(256) wgemm() {
    extern __shared__ char smem[];
    const int z = blockIdx.z;
    const int m0 = blockIdx.y * BM, n0 = blockIdx.x * BN;
    float acc[4][4][4];
    if (z == 0) {
        gemm_body(g_wqT_hi, g_wqT_lo, g_wkT_hi, g_wkT_lo, true, DMOD, m0, n0, smem, acc);
        EPI_LOOP({
            long o = (long)(m0 + mloc) * DMOD + n0 + nloc;
            f16 h = __float2half_rn(v);
            g_m_hi[o] = h;
            g_m_lo[o] = __float2half_rn(v - __half2float(h));
        })
    } else {
        gemm_body(g_wo, nullptr, g_wvT, nullptr, false, DMOD, m0, n0, smem, acc);
        EPI_LOOP({
            g_wc[(long)(m0 + mloc) * DMOD + n0 + nloc] = __float2half_rn(v);
        })
    }
}

// ----------------------------------------------------------------------------
// fused projections: grid (8,64,2). z=0: zk = xk @ M^T (3P, single out);
//                                   z=1: u = xv @ Wc^T (1P, out transposed [B][D][S]).
// ----------------------------------------------------------------------------
__global__ void __launch_bounds__(256) proj2() {
    extern __shared__ char smem[];
    const int z = blockIdx.z;
    const int m0 = blockIdx.y * BM, n0 = blockIdx.x * BN;
    float acc[4][4][4];
    if (z == 0) {
        gemm_body(g_xk_hi, g_xk_lo, g_m_hi, g_m_lo, true, DMOD, m0, n0, smem, acc);
        EPI_LOOP({
            g_zk[(long)(m0 + mloc) * DMOD + n0 + nloc] = __float2half_rn(v);
        })
    } else {
        gemm_body(g_xv, nullptr, g_wc, nullptr, false, DMOD, m0, n0, smem, acc);
        EPI_LOOP({
            const int m = m0 + mloc;
            g_uT[(long)(m >> 11) * ((long)DMOD * SEQ) +
                 (long)(n0 + nloc) * SEQ + (m & 2047)] = __float2half_rn(v);
        })
    }
}

// ----------------------------------------------------------------------------
// scores: sc = 0.125 * xq_hi @ zk^T (batched), fp32 out
// ----------------------------------------------------------------------------
__global__ void __launch_bounds__(256) scores_g() {
    extern __shared__ char smem[];
    const long bz = blockIdx.z;
    const int m0 = blockIdx.y * BM, n0 = blockIdx.x * BN;
    float acc[4][4][4];
    gemm_body(g_xq_hi + bz * (long)SEQ * DMOD, nullptr,
              g_zk + bz * (long)SEQ * DMOD, nullptr,
              false, DMOD, m0, n0, smem, acc);
    float* C = g_sc + bz * (long)SEQ * SEQ;
    EPI_LOOP({
        C[(long)(m0 + mloc) * SEQ + n0 + nloc] = v * 0.125f;
    })
}

// ----------------------------------------------------------------------------
// out: out = P @ u + bc (batched), fp32 out direct
// ----------------------------------------------------------------------------
__global__ void __launch_bounds__(256) out_g(float* __restrict__ out) {
    extern __shared__ char smem[];
    const long bz = blockIdx.z;
    const int m0 = blockIdx.y * BM, n0 = blockIdx.x * BN;
    float acc[4][4][4];
    gemm_body(g_at + bz * (long)SEQ * SEQ, nullptr,
              g_uT + bz * (long)DMOD * SEQ, nullptr,
              false, SEQ, m0, n0, smem, acc);
    float* C = out + bz * (long)SEQ * DMOD;
    EPI_LOOP({
        const int n = n0 + nloc;
        C[(long)(m0 + mloc) * DMOD + n] = v + __ldg(g_bc + n);
    })
}

// ----------------------------------------------------------------------------
// launch
// ----------------------------------------------------------------------------
extern "C" void kernel_launch(void* const* d_in, const int* in_sizes, int n_in,
                              void* d_out, int out_size) {
    const float* q  = (const float*)d_in[0];
    const float* k  = (const float*)d_in[1];
    const float* v  = (const float*)d_in[2];
    const float* Wq = (const float*)d_in[3];
    const float* bq = (const float*)d_in[4];
    const float* Wk = (const float*)d_in[5];
    const float* bk = (const float*)d_in[6];
    const float* Wv = (const float*)d_in[7];
    const float* bv = (const float*)d_in[8];
    const float* Wo = (const float*)d_in[9];
    const float* bo = (const float*)d_in[10];
    float* out = (float*)d_out;
    (void)bk;  // bk-dependent per-row terms cancel in softmax

    float* sc; f16* at;
    cudaGetSymbolAddress((void**)&sc, g_sc);
    cudaGetSymbolAddress((void**)&at, g_at);

    cudaFuncSetAttribute(wgemm,    cudaFuncAttributeMaxDynamicSharedMemorySize, SMEM3);
    cudaFuncSetAttribute(proj2,    cudaFuncAttributeMaxDynamicSharedMemorySize, SMEM3);
    cudaFuncSetAttribute(scores_g, cudaFuncAttributeMaxDynamicSharedMemorySize, SMEM1);
    cudaFuncSetAttribute(out_g,    cudaFuncAttributeMaxDynamicSharedMemorySize, SMEM1);

    const int S = SEQ, B = BATCH;
    dim3 blk(256);

    // 1: conversions (xq/xk pairs, xv, wo)
    const long NCONV = 3 * NQ + NW;
    conv_all<<<(unsigned)((NCONV + 511) / 512), 512>>>(q, k, v, Wo);
    // 2: transposes (WqT/WkT pairs, WvT single)
    transp3<<<dim3(32, 32, 3), dim3(32, 8)>>>(Wq, Wk, Wv);
    // 3: bc and w1
    small_bias<<<1028, 256>>>(bv, Wo, bo, bq, Wk);
    // 4: rk = 0.125 * xk @ w1
    rk_gemv<<<(unsigned)NBS, 256>>>(k);
    // 5: M (3P pair) + Wc (1P)
    wgemm<<<dim3(8, 8, 2), blk, SMEM3>>>();
    // 6: zk (3P) + uT (1P)                              <-- ncu -s 5 -c 1 capture
    proj2<<<dim3(8, 64, 2), blk, SMEM3>>>();
    // 7: scores = 0.125 * xq_hi @ zk^T
    scores_g<<<dim3(16, 16, B), blk, SMEM1>>>();
    // 8: softmax (+rk column correction) -> fp16 probs
    softmax_f16<<<(unsigned)(B * S), 256>>>(sc, at, S);
    // 9: out = P @ u + bc
    out_g<<<dim3(8, 16, B), blk, SMEM1>>>(out);
}